// round 7
// baseline (speedup 1.0000x reference)
#include <cuda_runtime.h>
#include <cuda_bf16.h>
#include <mma.h>
#include <math.h>

using namespace nvcuda;

#define NB 8
#define NF 128
#define LATD 256
#define NPIX 4096
#define NCALLS 16
#define FIN 384
#define FO 256
#define KT 197376

#define OFF_WIN  0
#define OFF_BIN  49152
#define OFF_WMID 49280
#define OFF_BMID 65664
#define OFF_WOUT 65792
#define OFF_BOUT 98560
#define OFF_WSH  98816
#define OFF_BSH  197120

// -------- scratch --------
__device__ __align__(16) float g_kall[NB * KT];
__device__ __align__(16) __nv_bfloat16 g_ph[NB * FIN * NPIX], g_pl[NB * FIN * NPIX];
__device__ __align__(16) __nv_bfloat16 g_h1h[NB * NF * NPIX], g_h1l[NB * NF * NPIX];
__device__ __align__(16) __nv_bfloat16 g_h2h[NB * NF * NPIX], g_h2l[NB * NF * NPIX];
__device__ __align__(16) __nv_bfloat16 g_w1h[NB * 128 * 384], g_w1l[NB * 128 * 384];
__device__ __align__(16) __nv_bfloat16 g_w2h[NB * 128 * 128], g_w2l[NB * 128 * 128];
__device__ __align__(16) __nv_bfloat16 g_w3h[NB * 256 * 512], g_w3l[NB * 256 * 512];
__device__ __align__(16) float g_c1[NB * NF * NPIX];
__device__ __align__(16) float g_c2[NB * NF * NPIX];

#define CP16(dst, src) \
    asm volatile("cp.async.cg.shared.global [%0], [%1], 16;\n" :: "r"(dst), "l"(src))
#define CP16A(dst, src) \
    asm volatile("cp.async.ca.shared.global [%0], [%1], 16;\n" :: "r"(dst), "l"(src))
#define CP_COMMIT() asm volatile("cp.async.commit_group;\n" ::: "memory")
#define CP_WAIT(n)  asm volatile("cp.async.wait_group %0;\n" :: "n"(n) : "memory")

__device__ __forceinline__ void split1(float v, __nv_bfloat16& h, __nv_bfloat16& l) {
    unsigned iv = __float_as_uint(v) & 0xFFFF0000u;
    h = __ushort_as_bfloat16((unsigned short)(iv >> 16));
    l = __float2bfloat16(v - __uint_as_float(iv));
}

// ======================================================================
// hyper + pack fused: bias segs -> kall; weight segs -> bf16 hi/lo planes
// ======================================================================
__global__ void __launch_bounds__(256) hyper_kernel(
    const float* __restrict__ lat, const float* __restrict__ hw,
    const float* __restrict__ hb, float* __restrict__ kall)
{
    __shared__ float ls[NB * LATD];
    const int tid = threadIdx.x;
    for (int i = tid; i < NB * LATD; i += 256) ls[i] = lat[i];
    __syncthreads();
    const int n = blockIdx.x * 256 + tid;
    float acc[NB];
#pragma unroll
    for (int b = 0; b < NB; b++) acc[b] = 0.f;
    for (int k = 0; k < LATD; k++) {
        float w = hw[(size_t)k * KT + n];
#pragma unroll
        for (int b = 0; b < NB; b++) acc[b] = fmaf(ls[b * LATD + k], w, acc[b]);
    }
    const float bias = hb[n];

    float s = 1.f;
    int kind;           // 0=w1, 1=w2, 2=w3, 3=bias
    size_t widx = 0;
    if (n < OFF_BIN) {
        s = 0.05103103630798288f; kind = 0; widx = n;
    } else if (n < OFF_WMID) {
        kind = 3;
    } else if (n < OFF_BMID) {
        s = 0.08838834764831845f; kind = 1; widx = n - OFF_WMID;
    } else if (n < OFF_WOUT) {
        kind = 3;
    } else if (n < OFF_BOUT) {
        s = 0.08838834764831845f; kind = 2;
        int i = n - OFF_WOUT;
        widx = (size_t)(i >> 7) * 512 + (i & 127);
    } else if (n < OFF_WSH) {
        kind = 3;
    } else if (n < OFF_BSH) {
        s = 0.05103103630798288f; kind = 2;
        int i = n - OFF_WSH;
        widx = (size_t)(i / 384) * 512 + 128 + (i % 384);
    } else {
        kind = 3;
    }

#pragma unroll
    for (int b = 0; b < NB; b++) {
        float v = (acc[b] + bias) * s;
        if (kind == 3) {
            kall[(size_t)b * KT + n] = v;
        } else {
            __nv_bfloat16 h, l;
            split1(v, h, l);
            if (kind == 0) {
                g_w1h[(size_t)b * 49152 + widx] = h;
                g_w1l[(size_t)b * 49152 + widx] = l;
            } else if (kind == 1) {
                g_w2h[(size_t)b * 16384 + widx] = h;
                g_w2l[(size_t)b * 16384 + widx] = l;
            } else {
                g_w3h[(size_t)b * 131072 + widx] = h;
                g_w3l[(size_t)b * 131072 + widx] = l;
            }
        }
    }
}

// ======================================================================
// build_p: instance-norm(concat[x, sobel_x, sobel_y]) -> hi/lo bf16 planes
// ======================================================================
__global__ void __launch_bounds__(256) build_p_kernel(
    const float* __restrict__ X, __nv_bfloat16* __restrict__ Ph,
    __nv_bfloat16* __restrict__ Pl)
{
    const int c = blockIdx.x, b = blockIdx.y, tid = threadIdx.x;
    __shared__ float sp[68 * 68];
    __shared__ float red[8][6];
    __shared__ float stats[6];
    for (int i = tid; i < 68 * 68; i += 256) sp[i] = 0.f;
    __syncthreads();
    const float* Xp = X + ((size_t)b * NF + c) * NPIX;
    for (int i = tid; i < NPIX; i += 256) {
        int y = i >> 6, x = i & 63;
        sp[(y + 2) * 68 + (x + 2)] = Xp[i];
    }
    __syncthreads();
    const float C = 0.70710678118654752f;
    float vx[16], vsx[16], vsy[16];
    float s0 = 0.f, q0 = 0.f, s1 = 0.f, q1 = 0.f, s2 = 0.f, q2 = 0.f;
#pragma unroll
    for (int it = 0; it < 16; it++) {
        int pix = tid + it * 256;
        int y = pix >> 6, x = pix & 63;
        const float* B = &sp[y * 68 + x];
        float xv = B[2*68+2];
        float sx = C*(B[1*68+4]-B[1*68+0]) + 0.5f*(B[1*68+3]-B[1*68+1])
                 + (B[2*68+4]-B[2*68+0]) + C*(B[2*68+3]-B[2*68+1])
                 + C*(B[3*68+4]-B[3*68+0]) + 0.5f*(B[3*68+3]-B[3*68+1]);
        float sy = C*(B[4*68+1]-B[0*68+1]) + (B[4*68+2]-B[0*68+2])
                 + C*(B[4*68+3]-B[0*68+3])
                 + 0.5f*(B[3*68+1]-B[1*68+1]) + C*(B[3*68+2]-B[1*68+2])
                 + 0.5f*(B[3*68+3]-B[1*68+3]);
        vx[it] = xv; vsx[it] = sx; vsy[it] = sy;
        s0 += xv; q0 = fmaf(xv, xv, q0);
        s1 += sx; q1 = fmaf(sx, sx, q1);
        s2 += sy; q2 = fmaf(sy, sy, q2);
    }
#pragma unroll
    for (int off = 16; off; off >>= 1) {
        s0 += __shfl_down_sync(~0u, s0, off); q0 += __shfl_down_sync(~0u, q0, off);
        s1 += __shfl_down_sync(~0u, s1, off); q1 += __shfl_down_sync(~0u, q1, off);
        s2 += __shfl_down_sync(~0u, s2, off); q2 += __shfl_down_sync(~0u, q2, off);
    }
    if ((tid & 31) == 0) {
        int w = tid >> 5;
        red[w][0]=s0; red[w][1]=q0; red[w][2]=s1; red[w][3]=q1; red[w][4]=s2; red[w][5]=q2;
    }
    __syncthreads();
    if (tid == 0) {
        float S[6] = {0,0,0,0,0,0};
        for (int w = 0; w < 8; w++) for (int j = 0; j < 6; j++) S[j] += red[w][j];
        const float invN = 1.f / 4096.f;
#pragma unroll
        for (int t3 = 0; t3 < 3; t3++) {
            float mu = S[2*t3] * invN;
            float var = fmaxf(S[2*t3+1] * invN - mu*mu, 0.f);
            stats[2*t3] = mu; stats[2*t3+1] = rsqrtf(var + 1e-5f);
        }
    }
    __syncthreads();
    const float mu0 = stats[0], in0 = stats[1], mu1 = stats[2], in1 = stats[3],
                mu2 = stats[4], in2 = stats[5];
    const size_t p0 = ((size_t)b * FIN + c) * NPIX;
#pragma unroll
    for (int it = 0; it < 16; it++) {
        int pix = tid + it * 256;
        float v0 = (vx[it]  - mu0) * in0;
        float v1 = (vsx[it] - mu1) * in1;
        float v2 = (vsy[it] - mu2) * in2;
        __nv_bfloat16 h, l;
        split1(v0, h, l); Ph[p0 + pix] = h; Pl[p0 + pix] = l;
        split1(v1, h, l); Ph[p0 + (size_t)NF*NPIX + pix] = h;   Pl[p0 + (size_t)NF*NPIX + pix] = l;
        split1(v2, h, l); Ph[p0 + (size_t)2*NF*NPIX + pix] = h; Pl[p0 + (size_t)2*NF*NPIX + pix] = l;
    }
}

// ======================================================================
// wmma bf16 GEMM, hi/lo 3-term, cp.async pipelined.
// MBLKS=1: 3-stage, 1 sync/chunk. MBLKS=2: 2-stage.
// NOTE: all smem row strides must keep 16B-aligned rows (BW*2 % 16 == 0).
// ======================================================================
template<int MBLKS>
__global__ void __launch_bounds__(256, 2) gemm_wmma(
    const __nv_bfloat16* __restrict__ Wh, const __nv_bfloat16* __restrict__ Wl,
    int Ktot,
    const __nv_bfloat16* __restrict__ B1h, const __nv_bfloat16* __restrict__ B1l,
    int K1,
    const __nv_bfloat16* __restrict__ B2h, const __nv_bfloat16* __restrict__ B2l,
    const float* __restrict__ kall, int boff1, int boff2,
    float* __restrict__ outf,
    __nv_bfloat16* __restrict__ outh, __nv_bfloat16* __restrict__ outl,
    const float* __restrict__ xold, const float* __restrict__ leakp)
{
    constexpr int MT = MBLKS * 128;
    constexpr int NT = 128 / MBLKS;
    constexpr int AW = 40;                       // 80B rows (16B-mult)
    constexpr int BW = (MBLKS == 1) ? 136 : 72;  // 272B / 144B rows (16B-mult)
    constexpr int EW = NT + 4;
    constexpr int BUFE = 2 * MT * AW + 2 * 32 * BW;

    extern __shared__ __align__(16) char sm[];
    __nv_bfloat16* smB = (__nv_bfloat16*)sm;
    float* Es = (float*)sm;

    const int tid = threadIdx.x;
    const int b = blockIdx.y;
    const int n0 = blockIdx.x * NT;
    const int wid = tid >> 5;
    const int wm = (MBLKS == 1) ? (wid >> 1) : wid;
    const int wn = (MBLKS == 1) ? (wid & 1) : 0;

    const __nv_bfloat16* WhB = Wh + (size_t)b * MT * Ktot;
    const __nv_bfloat16* WlB = Wl + (size_t)b * MT * Ktot;

    wmma::fragment<wmma::accumulator, 16, 16, 16, float> acc[2][4];
#pragma unroll
    for (int i = 0; i < 2; i++)
#pragma unroll
        for (int j = 0; j < 4; j++) wmma::fill_fragment(acc[i][j], 0.f);

    auto stage = [&](int kc, int s) {
        __nv_bfloat16* Ahd = smB + (size_t)s * BUFE;
        __nv_bfloat16* Ald = Ahd + MT * AW;
        __nv_bfloat16* Bhd = Ald + MT * AW;
        __nv_bfloat16* Bld = Bhd + 32 * BW;
#pragma unroll
        for (int i = tid; i < MT * 8; i += 256) {
            int plane = (i >= MT * 4);
            int rem = i - plane * MT * 4;
            int m = rem >> 2, q = rem & 3;
            const __nv_bfloat16* src = (plane ? WlB : WhB) + (size_t)m * Ktot + kc + q * 8;
            unsigned d = (unsigned)__cvta_generic_to_shared(
                (plane ? Ald : Ahd) + m * AW + q * 8);
            CP16A(d, src);
        }
        const __nv_bfloat16 *sh, *sl; int ch0;
        if (kc < K1) {
            sh = B1h + (size_t)b * K1 * NPIX; sl = B1l + (size_t)b * K1 * NPIX; ch0 = kc;
        } else {
            int K2 = Ktot - K1;
            sh = B2h + (size_t)b * K2 * NPIX; sl = B2l + (size_t)b * K2 * NPIX; ch0 = kc - K1;
        }
        constexpr int NC8 = NT / 8;
#pragma unroll
        for (int i = tid; i < 32 * NC8 * 2; i += 256) {
            int plane = (i >= 32 * NC8);
            int rem = i - plane * 32 * NC8;
            int k = rem / NC8, c = (rem - k * NC8) * 8;
            const __nv_bfloat16* src = (plane ? sl : sh) + (size_t)(ch0 + k) * NPIX + n0 + c;
            unsigned d = (unsigned)__cvta_generic_to_shared(
                (plane ? Bld : Bhd) + k * BW + c);
            CP16(d, src);
        }
        CP_COMMIT();
    };

    auto compute = [&](int s) {
        const __nv_bfloat16* Ahd = smB + (size_t)s * BUFE;
        const __nv_bfloat16* Ald = Ahd + MT * AW;
        const __nv_bfloat16* Bhd = Ald + MT * AW;
        const __nv_bfloat16* Bld = Bhd + 32 * BW;
#pragma unroll
        for (int kk = 0; kk < 2; kk++) {
            wmma::fragment<wmma::matrix_a, 16, 16, 16, __nv_bfloat16, wmma::row_major> ah[2], al[2];
            wmma::fragment<wmma::matrix_b, 16, 16, 16, __nv_bfloat16, wmma::row_major> bh[4], bl[4];
#pragma unroll
            for (int i = 0; i < 2; i++) {
                wmma::load_matrix_sync(ah[i], Ahd + (wm * 32 + i * 16) * AW + kk * 16, AW);
                wmma::load_matrix_sync(al[i], Ald + (wm * 32 + i * 16) * AW + kk * 16, AW);
            }
#pragma unroll
            for (int j = 0; j < 4; j++) {
                wmma::load_matrix_sync(bh[j], Bhd + kk * 16 * BW + wn * 64 + j * 16, BW);
                wmma::load_matrix_sync(bl[j], Bld + kk * 16 * BW + wn * 64 + j * 16, BW);
            }
#pragma unroll
            for (int i = 0; i < 2; i++)
#pragma unroll
                for (int j = 0; j < 4; j++) {
                    wmma::mma_sync(acc[i][j], ah[i], bh[j], acc[i][j]);
                    wmma::mma_sync(acc[i][j], ah[i], bl[j], acc[i][j]);
                    wmma::mma_sync(acc[i][j], al[i], bh[j], acc[i][j]);
                }
        }
    };

    const int nch = Ktot >> 5;
    if (MBLKS == 1) {
        // 3-stage, single sync per chunk
        stage(0, 0);
        stage(32, 1);
        CP_WAIT(1);
        __syncthreads();
        for (int ic = 0; ic < nch; ic++) {
            compute(ic % 3);
            if (ic + 2 < nch) {
                stage((ic + 2) * 32, (ic + 2) % 3);
                CP_WAIT(1);
            } else {
                CP_WAIT(0);
            }
            __syncthreads();
        }
    } else {
        // 2-stage
        stage(0, 0);
        for (int ic = 0; ic < nch; ic++) {
            if (ic + 1 < nch) {
                stage((ic + 1) * 32, (ic + 1) & 1);
                CP_WAIT(1);
            } else {
                CP_WAIT(0);
            }
            __syncthreads();
            compute(ic & 1);
            __syncthreads();
        }
    }

#pragma unroll
    for (int i = 0; i < 2; i++)
#pragma unroll
        for (int j = 0; j < 4; j++)
            wmma::store_matrix_sync(Es + (wm * 32 + i * 16) * EW + wn * 64 + j * 16,
                                    acc[i][j], EW, wmma::mem_row_major);
    __syncthreads();

    const int m = tid >> 1, seg = tid & 1;
    if (MBLKS == 1) {
        const float bias = kall[(size_t)b * KT + boff1 + m];
        const size_t base = ((size_t)b * 128 + m) * NPIX + n0 + seg * 64;
        const float* er = Es + m * EW + seg * 64;
#pragma unroll
        for (int c = 0; c < 64; c += 2) {
            float v0 = fmaxf(er[c + 0] + bias, 0.f);
            float v1 = fmaxf(er[c + 1] + bias, 0.f);
            __nv_bfloat16 h0, l0, h1, l1;
            split1(v0, h0, l0);
            split1(v1, h1, l1);
            __nv_bfloat162 hp; hp.x = h0; hp.y = h1;
            __nv_bfloat162 lp; lp.x = l0; lp.y = l1;
            *reinterpret_cast<__nv_bfloat162*>(&outh[base + c]) = hp;
            *reinterpret_cast<__nv_bfloat162*>(&outl[base + c]) = lp;
        }
    } else {
        const float leak = fminf(fmaxf(leakp[0], 0.001f), 1000.f);
        const float* ka = kall + (size_t)b * KT;
        const float bv = ka[boff1 + m] + ka[boff2 + m];
        const float bg = ka[boff1 + 128 + m] + ka[boff2 + 128 + m];
        const size_t base = ((size_t)b * 128 + m) * NPIX + n0 + seg * 32;
        const float* ev = Es + m * EW + seg * 32;
        const float* eg = Es + (m + 128) * EW + seg * 32;
#pragma unroll
        for (int c = 0; c < 32; c += 4) {
            float4 x = *reinterpret_cast<const float4*>(&xold[base + c]);
            float4 o;
            { float v = ev[c+0] + bv, g = eg[c+0] + bg; o.x = x.x + leak * v / (1.f + __expf(-g)); }
            { float v = ev[c+1] + bv, g = eg[c+1] + bg; o.y = x.y + leak * v / (1.f + __expf(-g)); }
            { float v = ev[c+2] + bv, g = eg[c+2] + bg; o.z = x.z + leak * v / (1.f + __expf(-g)); }
            { float v = ev[c+3] + bv, g = eg[c+3] + bg; o.w = x.w + leak * v / (1.f + __expf(-g)); }
            *reinterpret_cast<float4*>(&outf[base + c]) = o;
        }
    }
}

// ======================================================================
// fp32 3x3 convs
// ======================================================================
__global__ void __launch_bounds__(256) conv3x3_kernel(
    const float* __restrict__ X, const float* __restrict__ W,
    const float* __restrict__ bias, const float* __restrict__ X0,
    float* __restrict__ Y, int act)
{
    const int b = blockIdx.z, o0 = blockIdx.y * 32, y0 = blockIdx.x * 4;
    const int tid = threadIdx.x;
    const int og = tid >> 5, pg = tid & 31, r = pg >> 3, xb = (pg & 7) * 8;
    __shared__ float sIn[6][66];
    __shared__ float sW[32 * 9];
    float acc[4][8];
#pragma unroll
    for (int oi = 0; oi < 4; oi++)
#pragma unroll
        for (int px = 0; px < 8; px++) acc[oi][px] = 0.f;
    const float* Xb = X + (size_t)b * NF * NPIX;
    for (int ci = 0; ci < NF; ci++) {
        __syncthreads();
        for (int i = tid; i < 6 * 66; i += 256) {
            int ry = i / 66, cx = i - ry * 66;
            int gy = y0 - 1 + ry, gx = cx - 1;
            float v = 0.f;
            if ((unsigned)gy < 64u && (unsigned)gx < 64u)
                v = Xb[(size_t)ci * NPIX + gy * 64 + gx];
            sIn[ry][cx] = v;
        }
        for (int i = tid; i < 288; i += 256) {
            int oi = i / 9, j = i - oi * 9;
            sW[i] = W[(size_t)(o0 + oi) * 1152 + ci * 9 + j];
        }
        __syncthreads();
        float in[3][10];
#pragma unroll
        for (int dy = 0; dy < 3; dy++)
#pragma unroll
            for (int dx = 0; dx < 10; dx++) in[dy][dx] = sIn[r + dy][xb + dx];
#pragma unroll
        for (int oi = 0; oi < 4; oi++) {
            float wr[9];
#pragma unroll
            for (int j = 0; j < 9; j++) wr[j] = sW[(og * 4 + oi) * 9 + j];
#pragma unroll
            for (int px = 0; px < 8; px++) {
                float s = acc[oi][px];
#pragma unroll
                for (int dy = 0; dy < 3; dy++)
#pragma unroll
                    for (int dx = 0; dx < 3; dx++)
                        s = fmaf(in[dy][px + dx], wr[dy * 3 + dx], s);
                acc[oi][px] = s;
            }
        }
    }
#pragma unroll
    for (int oi = 0; oi < 4; oi++) {
        const int o = o0 + og * 4 + oi;
        const float bvv = bias[o];
#pragma unroll
        for (int px = 0; px < 8; px++) {
            size_t idx = ((size_t)b * NF + o) * NPIX + (size_t)(y0 + r) * 64 + xb + px;
            float v = acc[oi][px] + bvv;
            if (X0) v += X0[idx];
            if (act) v = fmaxf(v, 0.f);
            Y[idx] = v;
        }
    }
}

__global__ void __launch_bounds__(256) conv_img_kernel(
    const float* __restrict__ X, const float* __restrict__ W,
    const float* __restrict__ bias,
    float* __restrict__ out_img, float* __restrict__ out_raw)
{
    const int b = blockIdx.y, y0 = blockIdx.x * 4, tid = threadIdx.x;
    const int r = tid >> 6, x = tid & 63;
    __shared__ float sW[3 * 1152];
    __shared__ float sIn[6][66];
    for (int i = tid; i < 3 * 1152; i += 256) sW[i] = W[i];
    float acc[3] = {0.f, 0.f, 0.f};
    const float* Xb = X + (size_t)b * NF * NPIX;
    for (int ci = 0; ci < NF; ci++) {
        __syncthreads();
        for (int i = tid; i < 6 * 66; i += 256) {
            int ry = i / 66, cx = i - ry * 66;
            int gy = y0 - 1 + ry, gx = cx - 1;
            float v = 0.f;
            if ((unsigned)gy < 64u && (unsigned)gx < 64u)
                v = Xb[(size_t)ci * NPIX + gy * 64 + gx];
            sIn[ry][cx] = v;
        }
        __syncthreads();
        float in[9];
#pragma unroll
        for (int dy = 0; dy < 3; dy++)
#pragma unroll
            for (int dx = 0; dx < 3; dx++) in[dy * 3 + dx] = sIn[r + dy][x + dx];
#pragma unroll
        for (int o = 0; o < 3; o++)
#pragma unroll
            for (int j = 0; j < 9; j++)
                acc[o] = fmaf(in[j], sW[o * 1152 + ci * 9 + j], acc[o]);
    }
#pragma unroll
    for (int o = 0; o < 3; o++) {
        float v = acc[o] + bias[o];
        size_t idx = ((size_t)b * 3 + o) * NPIX + (size_t)(y0 + r) * 64 + x;
        out_raw[idx] = v;
        out_img[idx] = fminf(fmaxf(v, -1.f), 1.f);
    }
}

// ======================================================================
extern "C" void kernel_launch(void* const* d_in, const int* in_sizes, int n_in,
                              void* d_out, int out_size)
{
    const float* lat  = (const float*)d_in[0];
    const float* ca   = (const float*)d_in[1];
    const float* leak = (const float*)d_in[2];
    const float* hw   = (const float*)d_in[3];
    const float* hb   = (const float*)d_in[4];
    const float* rw1  = (const float*)d_in[5];
    const float* rb1  = (const float*)d_in[6];
    const float* rw2  = (const float*)d_in[7];
    const float* rb2  = (const float*)d_in[8];
    const float* iw   = (const float*)d_in[9];
    const float* ib   = (const float*)d_in[10];

    float* out = (float*)d_out;
    float* out_img = out;
    float* embs    = out + 98304;
    float* out_raw = out + 98304 + (size_t)17 * 4194304;

    float *kall, *c1, *c2;
    __nv_bfloat16 *ph, *pl, *h1h, *h1l, *h2h, *h2l;
    __nv_bfloat16 *w1h, *w1l, *w2h, *w2l, *w3h, *w3l;
    cudaGetSymbolAddress((void**)&kall, g_kall);
    cudaGetSymbolAddress((void**)&ph,  g_ph);  cudaGetSymbolAddress((void**)&pl,  g_pl);
    cudaGetSymbolAddress((void**)&h1h, g_h1h); cudaGetSymbolAddress((void**)&h1l, g_h1l);
    cudaGetSymbolAddress((void**)&h2h, g_h2h); cudaGetSymbolAddress((void**)&h2l, g_h2l);
    cudaGetSymbolAddress((void**)&w1h, g_w1h); cudaGetSymbolAddress((void**)&w1l, g_w1l);
    cudaGetSymbolAddress((void**)&w2h, g_w2h); cudaGetSymbolAddress((void**)&w2l, g_w2l);
    cudaGetSymbolAddress((void**)&w3h, g_w3h); cudaGetSymbolAddress((void**)&w3l, g_w3l);
    cudaGetSymbolAddress((void**)&c1, g_c1);
    cudaGetSymbolAddress((void**)&c2, g_c2);

    // MBLKS=1: 3 stages x (2*128*40 + 2*32*136) elems * 2B = 113664
    // MBLKS=2: 2 stages x (2*256*40 + 2*32*72)  elems * 2B = 100352
    const int SM1 = 113664;
    const int SM2 = 100352;
    cudaFuncSetAttribute(gemm_wmma<1>, cudaFuncAttributeMaxDynamicSharedMemorySize, SM1);
    cudaFuncSetAttribute(gemm_wmma<2>, cudaFuncAttributeMaxDynamicSharedMemorySize, SM2);

    hyper_kernel<<<KT / 256, 256>>>(lat, hw, hb, kall);
    cudaMemcpyAsync(embs, ca, (size_t)4194304 * sizeof(float), cudaMemcpyDeviceToDevice);

    for (int t = 0; t < NCALLS; t++) {
        float* x  = embs + (size_t)t * 4194304;
        float* xn = x + 4194304;

        build_p_kernel<<<dim3(NF, NB), 256>>>(x, ph, pl);
        gemm_wmma<1><<<dim3(32, NB), 256, SM1>>>(
            w1h, w1l, 384, ph, pl, 384, nullptr, nullptr,
            kall, OFF_BIN, 0, nullptr, h1h, h1l, nullptr, nullptr);
        gemm_wmma<1><<<dim3(32, NB), 256, SM1>>>(
            w2h, w2l, 128, h1h, h1l, 128, nullptr, nullptr,
            kall, OFF_BMID, 0, nullptr, h2h, h2l, nullptr, nullptr);
        gemm_wmma<2><<<dim3(64, NB), 256, SM2>>>(
            w3h, w3l, 512, h2h, h2l, 128, ph, pl,
            kall, OFF_BOUT, OFF_BSH, xn, nullptr, nullptr, x, leak);
    }

    float* xf = embs + (size_t)NCALLS * 4194304;
    conv3x3_kernel<<<dim3(16, 4, NB), 256>>>(xf, rw1, rb1, nullptr, c1, 1);
    conv3x3_kernel<<<dim3(16, 4, NB), 256>>>(c1, rw2, rb2, xf, c2, 0);
    conv_img_kernel<<<dim3(16, NB), 256>>>(c2, iw, ib, out_img, out_raw);
}

// round 8
// speedup vs baseline: 1.0323x; 1.0323x over previous
#include <cuda_runtime.h>
#include <cuda_bf16.h>
#include <mma.h>
#include <math.h>

using namespace nvcuda;

#define NB 8
#define NF 128
#define LATD 256
#define NPIX 4096
#define NCALLS 16
#define FIN 384
#define FO 256
#define KT 197376

#define OFF_WIN  0
#define OFF_BIN  49152
#define OFF_WMID 49280
#define OFF_BMID 65664
#define OFF_WOUT 65792
#define OFF_BOUT 98560
#define OFF_WSH  98816
#define OFF_BSH  197120

// -------- scratch --------
__device__ __align__(16) float g_kall[NB * KT];
__device__ __align__(16) __nv_bfloat16 g_ph[NB * FIN * NPIX], g_pl[NB * FIN * NPIX];
__device__ __align__(16) __nv_bfloat16 g_h1h[NB * NF * NPIX], g_h1l[NB * NF * NPIX];
__device__ __align__(16) __nv_bfloat16 g_h2h[NB * NF * NPIX], g_h2l[NB * NF * NPIX];
__device__ __align__(16) __nv_bfloat16 g_w1h[NB * 128 * 384], g_w1l[NB * 128 * 384];
__device__ __align__(16) __nv_bfloat16 g_w2h[NB * 128 * 128], g_w2l[NB * 128 * 128];
__device__ __align__(16) __nv_bfloat16 g_w3h[NB * 256 * 512], g_w3l[NB * 256 * 512];
__device__ __align__(16) float g_c1[NB * NF * NPIX];
__device__ __align__(16) float g_c2[NB * NF * NPIX];

// L2-only staging: .cg avoids L1 pollution (R7 post-mortem: .ca regressed g3)
#define CP16(dst, src) \
    asm volatile("cp.async.cg.shared.global [%0], [%1], 16;\n" :: "r"(dst), "l"(src))
#define CP_COMMIT() asm volatile("cp.async.commit_group;\n" ::: "memory")
#define CP_WAIT(n)  asm volatile("cp.async.wait_group %0;\n" :: "n"(n) : "memory")

__device__ __forceinline__ void split1(float v, __nv_bfloat16& h, __nv_bfloat16& l) {
    unsigned iv = __float_as_uint(v) & 0xFFFF0000u;
    h = __ushort_as_bfloat16((unsigned short)(iv >> 16));
    l = __float2bfloat16(v - __uint_as_float(iv));
}

// ======================================================================
// hyper + pack fused: bias segs -> kall; weight segs -> bf16 hi/lo planes
// ======================================================================
__global__ void __launch_bounds__(256) hyper_kernel(
    const float* __restrict__ lat, const float* __restrict__ hw,
    const float* __restrict__ hb, float* __restrict__ kall)
{
    __shared__ float ls[NB * LATD];
    const int tid = threadIdx.x;
    for (int i = tid; i < NB * LATD; i += 256) ls[i] = lat[i];
    __syncthreads();
    const int n = blockIdx.x * 256 + tid;
    float acc[NB];
#pragma unroll
    for (int b = 0; b < NB; b++) acc[b] = 0.f;
    for (int k = 0; k < LATD; k++) {
        float w = hw[(size_t)k * KT + n];
#pragma unroll
        for (int b = 0; b < NB; b++) acc[b] = fmaf(ls[b * LATD + k], w, acc[b]);
    }
    const float bias = hb[n];

    float s = 1.f;
    int kind;           // 0=w1, 1=w2, 2=w3, 3=bias
    size_t widx = 0;
    if (n < OFF_BIN) {
        s = 0.05103103630798288f; kind = 0; widx = n;
    } else if (n < OFF_WMID) {
        kind = 3;
    } else if (n < OFF_BMID) {
        s = 0.08838834764831845f; kind = 1; widx = n - OFF_WMID;
    } else if (n < OFF_WOUT) {
        kind = 3;
    } else if (n < OFF_BOUT) {
        s = 0.08838834764831845f; kind = 2;
        int i = n - OFF_WOUT;
        widx = (size_t)(i >> 7) * 512 + (i & 127);
    } else if (n < OFF_WSH) {
        kind = 3;
    } else if (n < OFF_BSH) {
        s = 0.05103103630798288f; kind = 2;
        int i = n - OFF_WSH;
        widx = (size_t)(i / 384) * 512 + 128 + (i % 384);
    } else {
        kind = 3;
    }

#pragma unroll
    for (int b = 0; b < NB; b++) {
        float v = (acc[b] + bias) * s;
        if (kind == 3) {
            kall[(size_t)b * KT + n] = v;
        } else {
            __nv_bfloat16 h, l;
            split1(v, h, l);
            if (kind == 0) {
                g_w1h[(size_t)b * 49152 + widx] = h;
                g_w1l[(size_t)b * 49152 + widx] = l;
            } else if (kind == 1) {
                g_w2h[(size_t)b * 16384 + widx] = h;
                g_w2l[(size_t)b * 16384 + widx] = l;
            } else {
                g_w3h[(size_t)b * 131072 + widx] = h;
                g_w3l[(size_t)b * 131072 + widx] = l;
            }
        }
    }
}

// ======================================================================
// build_p: instance-norm(concat[x, sobel_x, sobel_y]) -> hi/lo bf16 planes
// ======================================================================
__global__ void __launch_bounds__(256) build_p_kernel(
    const float* __restrict__ X, __nv_bfloat16* __restrict__ Ph,
    __nv_bfloat16* __restrict__ Pl)
{
    const int c = blockIdx.x, b = blockIdx.y, tid = threadIdx.x;
    __shared__ float sp[68 * 68];
    __shared__ float red[8][6];
    __shared__ float stats[6];
    for (int i = tid; i < 68 * 68; i += 256) sp[i] = 0.f;
    __syncthreads();
    const float* Xp = X + ((size_t)b * NF + c) * NPIX;
    for (int i = tid; i < NPIX; i += 256) {
        int y = i >> 6, x = i & 63;
        sp[(y + 2) * 68 + (x + 2)] = Xp[i];
    }
    __syncthreads();
    const float C = 0.70710678118654752f;
    float vx[16], vsx[16], vsy[16];
    float s0 = 0.f, q0 = 0.f, s1 = 0.f, q1 = 0.f, s2 = 0.f, q2 = 0.f;
#pragma unroll
    for (int it = 0; it < 16; it++) {
        int pix = tid + it * 256;
        int y = pix >> 6, x = pix & 63;
        const float* B = &sp[y * 68 + x];
        float xv = B[2*68+2];
        float sx = C*(B[1*68+4]-B[1*68+0]) + 0.5f*(B[1*68+3]-B[1*68+1])
                 + (B[2*68+4]-B[2*68+0]) + C*(B[2*68+3]-B[2*68+1])
                 + C*(B[3*68+4]-B[3*68+0]) + 0.5f*(B[3*68+3]-B[3*68+1]);
        float sy = C*(B[4*68+1]-B[0*68+1]) + (B[4*68+2]-B[0*68+2])
                 + C*(B[4*68+3]-B[0*68+3])
                 + 0.5f*(B[3*68+1]-B[1*68+1]) + C*(B[3*68+2]-B[1*68+2])
                 + 0.5f*(B[3*68+3]-B[1*68+3]);
        vx[it] = xv; vsx[it] = sx; vsy[it] = sy;
        s0 += xv; q0 = fmaf(xv, xv, q0);
        s1 += sx; q1 = fmaf(sx, sx, q1);
        s2 += sy; q2 = fmaf(sy, sy, q2);
    }
#pragma unroll
    for (int off = 16; off; off >>= 1) {
        s0 += __shfl_down_sync(~0u, s0, off); q0 += __shfl_down_sync(~0u, q0, off);
        s1 += __shfl_down_sync(~0u, s1, off); q1 += __shfl_down_sync(~0u, q1, off);
        s2 += __shfl_down_sync(~0u, s2, off); q2 += __shfl_down_sync(~0u, q2, off);
    }
    if ((tid & 31) == 0) {
        int w = tid >> 5;
        red[w][0]=s0; red[w][1]=q0; red[w][2]=s1; red[w][3]=q1; red[w][4]=s2; red[w][5]=q2;
    }
    __syncthreads();
    if (tid == 0) {
        float S[6] = {0,0,0,0,0,0};
        for (int w = 0; w < 8; w++) for (int j = 0; j < 6; j++) S[j] += red[w][j];
        const float invN = 1.f / 4096.f;
#pragma unroll
        for (int t3 = 0; t3 < 3; t3++) {
            float mu = S[2*t3] * invN;
            float var = fmaxf(S[2*t3+1] * invN - mu*mu, 0.f);
            stats[2*t3] = mu; stats[2*t3+1] = rsqrtf(var + 1e-5f);
        }
    }
    __syncthreads();
    const float mu0 = stats[0], in0 = stats[1], mu1 = stats[2], in1 = stats[3],
                mu2 = stats[4], in2 = stats[5];
    const size_t p0 = ((size_t)b * FIN + c) * NPIX;
#pragma unroll
    for (int it = 0; it < 16; it++) {
        int pix = tid + it * 256;
        float v0 = (vx[it]  - mu0) * in0;
        float v1 = (vsx[it] - mu1) * in1;
        float v2 = (vsy[it] - mu2) * in2;
        __nv_bfloat16 h, l;
        split1(v0, h, l); Ph[p0 + pix] = h; Pl[p0 + pix] = l;
        split1(v1, h, l); Ph[p0 + (size_t)NF*NPIX + pix] = h;   Pl[p0 + (size_t)NF*NPIX + pix] = l;
        split1(v2, h, l); Ph[p0 + (size_t)2*NF*NPIX + pix] = h; Pl[p0 + (size_t)2*NF*NPIX + pix] = l;
    }
}

// ======================================================================
// wmma bf16 GEMM, hi/lo 3-term, cp.async pipelined (.cg only).
// MBLKS=1: 3-stage, 1 sync/chunk. MBLKS=2: 2-stage, 2 sync/chunk.
// All smem row strides keep rows 16B-aligned (BW*2 % 16 == 0).
// ======================================================================
template<int MBLKS>
__global__ void __launch_bounds__(256, 2) gemm_wmma(
    const __nv_bfloat16* __restrict__ Wh, const __nv_bfloat16* __restrict__ Wl,
    int Ktot,
    const __nv_bfloat16* __restrict__ B1h, const __nv_bfloat16* __restrict__ B1l,
    int K1,
    const __nv_bfloat16* __restrict__ B2h, const __nv_bfloat16* __restrict__ B2l,
    const float* __restrict__ kall, int boff1, int boff2,
    float* __restrict__ outf,
    __nv_bfloat16* __restrict__ outh, __nv_bfloat16* __restrict__ outl,
    const float* __restrict__ xold, const float* __restrict__ leakp)
{
    constexpr int MT = MBLKS * 128;
    constexpr int NT = 128 / MBLKS;
    constexpr int AW = 40;                       // 80B rows
    constexpr int BW = (MBLKS == 1) ? 136 : 72;  // 272B / 144B rows
    constexpr int EW = NT + 4;
    constexpr int BUFE = 2 * MT * AW + 2 * 32 * BW;

    extern __shared__ __align__(16) char sm[];
    __nv_bfloat16* smB = (__nv_bfloat16*)sm;
    float* Es = (float*)sm;

    const int tid = threadIdx.x;
    const int b = blockIdx.y;
    const int n0 = blockIdx.x * NT;
    const int wid = tid >> 5;
    const int wm = (MBLKS == 1) ? (wid >> 1) : wid;
    const int wn = (MBLKS == 1) ? (wid & 1) : 0;

    const __nv_bfloat16* WhB = Wh + (size_t)b * MT * Ktot;
    const __nv_bfloat16* WlB = Wl + (size_t)b * MT * Ktot;

    wmma::fragment<wmma::accumulator, 16, 16, 16, float> acc[2][4];
#pragma unroll
    for (int i = 0; i < 2; i++)
#pragma unroll
        for (int j = 0; j < 4; j++) wmma::fill_fragment(acc[i][j], 0.f);

    auto stage = [&](int kc, int s) {
        __nv_bfloat16* Ahd = smB + (size_t)s * BUFE;
        __nv_bfloat16* Ald = Ahd + MT * AW;
        __nv_bfloat16* Bhd = Ald + MT * AW;
        __nv_bfloat16* Bld = Bhd + 32 * BW;
#pragma unroll
        for (int i = tid; i < MT * 8; i += 256) {
            int plane = (i >= MT * 4);
            int rem = i - plane * MT * 4;
            int m = rem >> 2, q = rem & 3;
            const __nv_bfloat16* src = (plane ? WlB : WhB) + (size_t)m * Ktot + kc + q * 8;
            unsigned d = (unsigned)__cvta_generic_to_shared(
                (plane ? Ald : Ahd) + m * AW + q * 8);
            CP16(d, src);
        }
        const __nv_bfloat16 *sh, *sl; int ch0;
        if (kc < K1) {
            sh = B1h + (size_t)b * K1 * NPIX; sl = B1l + (size_t)b * K1 * NPIX; ch0 = kc;
        } else {
            int K2 = Ktot - K1;
            sh = B2h + (size_t)b * K2 * NPIX; sl = B2l + (size_t)b * K2 * NPIX; ch0 = kc - K1;
        }
        constexpr int NC8 = NT / 8;
#pragma unroll
        for (int i = tid; i < 32 * NC8 * 2; i += 256) {
            int plane = (i >= 32 * NC8);
            int rem = i - plane * 32 * NC8;
            int k = rem / NC8, c = (rem - k * NC8) * 8;
            const __nv_bfloat16* src = (plane ? sl : sh) + (size_t)(ch0 + k) * NPIX + n0 + c;
            unsigned d = (unsigned)__cvta_generic_to_shared(
                (plane ? Bld : Bhd) + k * BW + c);
            CP16(d, src);
        }
        CP_COMMIT();
    };

    auto compute = [&](int s) {
        const __nv_bfloat16* Ahd = smB + (size_t)s * BUFE;
        const __nv_bfloat16* Ald = Ahd + MT * AW;
        const __nv_bfloat16* Bhd = Ald + MT * AW;
        const __nv_bfloat16* Bld = Bhd + 32 * BW;
#pragma unroll
        for (int kk = 0; kk < 2; kk++) {
            wmma::fragment<wmma::matrix_a, 16, 16, 16, __nv_bfloat16, wmma::row_major> ah[2], al[2];
            wmma::fragment<wmma::matrix_b, 16, 16, 16, __nv_bfloat16, wmma::row_major> bh[4], bl[4];
#pragma unroll
            for (int i = 0; i < 2; i++) {
                wmma::load_matrix_sync(ah[i], Ahd + (wm * 32 + i * 16) * AW + kk * 16, AW);
                wmma::load_matrix_sync(al[i], Ald + (wm * 32 + i * 16) * AW + kk * 16, AW);
            }
#pragma unroll
            for (int j = 0; j < 4; j++) {
                wmma::load_matrix_sync(bh[j], Bhd + kk * 16 * BW + wn * 64 + j * 16, BW);
                wmma::load_matrix_sync(bl[j], Bld + kk * 16 * BW + wn * 64 + j * 16, BW);
            }
#pragma unroll
            for (int i = 0; i < 2; i++)
#pragma unroll
                for (int j = 0; j < 4; j++) {
                    wmma::mma_sync(acc[i][j], ah[i], bh[j], acc[i][j]);
                    wmma::mma_sync(acc[i][j], ah[i], bl[j], acc[i][j]);
                    wmma::mma_sync(acc[i][j], al[i], bh[j], acc[i][j]);
                }
        }
    };

    const int nch = Ktot >> 5;
    if (MBLKS == 1) {
        // 3-stage, single sync per chunk
        stage(0, 0);
        stage(32, 1);
        CP_WAIT(1);
        __syncthreads();
        for (int ic = 0; ic < nch; ic++) {
            compute(ic % 3);
            if (ic + 2 < nch) {
                stage((ic + 2) * 32, (ic + 2) % 3);
                CP_WAIT(1);
            } else {
                CP_WAIT(0);
            }
            __syncthreads();
        }
    } else {
        // 2-stage, two syncs per chunk
        stage(0, 0);
        for (int ic = 0; ic < nch; ic++) {
            if (ic + 1 < nch) {
                stage((ic + 1) * 32, (ic + 1) & 1);
                CP_WAIT(1);
            } else {
                CP_WAIT(0);
            }
            __syncthreads();
            compute(ic & 1);
            __syncthreads();
        }
    }

#pragma unroll
    for (int i = 0; i < 2; i++)
#pragma unroll
        for (int j = 0; j < 4; j++)
            wmma::store_matrix_sync(Es + (wm * 32 + i * 16) * EW + wn * 64 + j * 16,
                                    acc[i][j], EW, wmma::mem_row_major);
    __syncthreads();

    const int m = tid >> 1, seg = tid & 1;
    if (MBLKS == 1) {
        const float bias = kall[(size_t)b * KT + boff1 + m];
        const size_t base = ((size_t)b * 128 + m) * NPIX + n0 + seg * 64;
        const float* er = Es + m * EW + seg * 64;
#pragma unroll
        for (int c = 0; c < 64; c += 2) {
            float v0 = fmaxf(er[c + 0] + bias, 0.f);
            float v1 = fmaxf(er[c + 1] + bias, 0.f);
            __nv_bfloat16 h0, l0, h1, l1;
            split1(v0, h0, l0);
            split1(v1, h1, l1);
            __nv_bfloat162 hp; hp.x = h0; hp.y = h1;
            __nv_bfloat162 lp; lp.x = l0; lp.y = l1;
            *reinterpret_cast<__nv_bfloat162*>(&outh[base + c]) = hp;
            *reinterpret_cast<__nv_bfloat162*>(&outl[base + c]) = lp;
        }
    } else {
        const float leak = fminf(fmaxf(leakp[0], 0.001f), 1000.f);
        const float* ka = kall + (size_t)b * KT;
        const float bv = ka[boff1 + m] + ka[boff2 + m];
        const float bg = ka[boff1 + 128 + m] + ka[boff2 + 128 + m];
        const size_t base = ((size_t)b * 128 + m) * NPIX + n0 + seg * 32;
        const float* ev = Es + m * EW + seg * 32;
        const float* eg = Es + (m + 128) * EW + seg * 32;
#pragma unroll
        for (int c = 0; c < 32; c += 4) {
            float4 x = *reinterpret_cast<const float4*>(&xold[base + c]);
            float4 o;
            { float v = ev[c+0] + bv, g = eg[c+0] + bg; o.x = x.x + leak * v / (1.f + __expf(-g)); }
            { float v = ev[c+1] + bv, g = eg[c+1] + bg; o.y = x.y + leak * v / (1.f + __expf(-g)); }
            { float v = ev[c+2] + bv, g = eg[c+2] + bg; o.z = x.z + leak * v / (1.f + __expf(-g)); }
            { float v = ev[c+3] + bv, g = eg[c+3] + bg; o.w = x.w + leak * v / (1.f + __expf(-g)); }
            *reinterpret_cast<float4*>(&outf[base + c]) = o;
        }
    }
}

// ======================================================================
// fp32 3x3 convs
// ======================================================================
__global__ void __launch_bounds__(256) conv3x3_kernel(
    const float* __restrict__ X, const float* __restrict__ W,
    const float* __restrict__ bias, const float* __restrict__ X0,
    float* __restrict__ Y, int act)
{
    const int b = blockIdx.z, o0 = blockIdx.y * 32, y0 = blockIdx.x * 4;
    const int tid = threadIdx.x;
    const int og = tid >> 5, pg = tid & 31, r = pg >> 3, xb = (pg & 7) * 8;
    __shared__ float sIn[6][66];
    __shared__ float sW[32 * 9];
    float acc[4][8];
#pragma unroll
    for (int oi = 0; oi < 4; oi++)
#pragma unroll
        for (int px = 0; px < 8; px++) acc[oi][px] = 0.f;
    const float* Xb = X + (size_t)b * NF * NPIX;
    for (int ci = 0; ci < NF; ci++) {
        __syncthreads();
        for (int i = tid; i < 6 * 66; i += 256) {
            int ry = i / 66, cx = i - ry * 66;
            int gy = y0 - 1 + ry, gx = cx - 1;
            float v = 0.f;
            if ((unsigned)gy < 64u && (unsigned)gx < 64u)
                v = Xb[(size_t)ci * NPIX + gy * 64 + gx];
            sIn[ry][cx] = v;
        }
        for (int i = tid; i < 288; i += 256) {
            int oi = i / 9, j = i - oi * 9;
            sW[i] = W[(size_t)(o0 + oi) * 1152 + ci * 9 + j];
        }
        __syncthreads();
        float in[3][10];
#pragma unroll
        for (int dy = 0; dy < 3; dy++)
#pragma unroll
            for (int dx = 0; dx < 10; dx++) in[dy][dx] = sIn[r + dy][xb + dx];
#pragma unroll
        for (int oi = 0; oi < 4; oi++) {
            float wr[9];
#pragma unroll
            for (int j = 0; j < 9; j++) wr[j] = sW[(og * 4 + oi) * 9 + j];
#pragma unroll
            for (int px = 0; px < 8; px++) {
                float s = acc[oi][px];
#pragma unroll
                for (int dy = 0; dy < 3; dy++)
#pragma unroll
                    for (int dx = 0; dx < 3; dx++)
                        s = fmaf(in[dy][px + dx], wr[dy * 3 + dx], s);
                acc[oi][px] = s;
            }
        }
    }
#pragma unroll
    for (int oi = 0; oi < 4; oi++) {
        const int o = o0 + og * 4 + oi;
        const float bvv = bias[o];
#pragma unroll
        for (int px = 0; px < 8; px++) {
            size_t idx = ((size_t)b * NF + o) * NPIX + (size_t)(y0 + r) * 64 + xb + px;
            float v = acc[oi][px] + bvv;
            if (X0) v += X0[idx];
            if (act) v = fmaxf(v, 0.f);
            Y[idx] = v;
        }
    }
}

__global__ void __launch_bounds__(256) conv_img_kernel(
    const float* __restrict__ X, const float* __restrict__ W,
    const float* __restrict__ bias,
    float* __restrict__ out_img, float* __restrict__ out_raw)
{
    const int b = blockIdx.y, y0 = blockIdx.x * 4, tid = threadIdx.x;
    const int r = tid >> 6, x = tid & 63;
    __shared__ float sW[3 * 1152];
    __shared__ float sIn[6][66];
    for (int i = tid; i < 3 * 1152; i += 256) sW[i] = W[i];
    float acc[3] = {0.f, 0.f, 0.f};
    const float* Xb = X + (size_t)b * NF * NPIX;
    for (int ci = 0; ci < NF; ci++) {
        __syncthreads();
        for (int i = tid; i < 6 * 66; i += 256) {
            int ry = i / 66, cx = i - ry * 66;
            int gy = y0 - 1 + ry, gx = cx - 1;
            float v = 0.f;
            if ((unsigned)gy < 64u && (unsigned)gx < 64u)
                v = Xb[(size_t)ci * NPIX + gy * 64 + gx];
            sIn[ry][cx] = v;
        }
        __syncthreads();
        float in[9];
#pragma unroll
        for (int dy = 0; dy < 3; dy++)
#pragma unroll
            for (int dx = 0; dx < 3; dx++) in[dy * 3 + dx] = sIn[r + dy][x + dx];
#pragma unroll
        for (int o = 0; o < 3; o++)
#pragma unroll
            for (int j = 0; j < 9; j++)
                acc[o] = fmaf(in[j], sW[o * 1152 + ci * 9 + j], acc[o]);
    }
#pragma unroll
    for (int o = 0; o < 3; o++) {
        float v = acc[o] + bias[o];
        size_t idx = ((size_t)b * 3 + o) * NPIX + (size_t)(y0 + r) * 64 + x;
        out_raw[idx] = v;
        out_img[idx] = fminf(fmaxf(v, -1.f), 1.f);
    }
}

// ======================================================================
extern "C" void kernel_launch(void* const* d_in, const int* in_sizes, int n_in,
                              void* d_out, int out_size)
{
    const float* lat  = (const float*)d_in[0];
    const float* ca   = (const float*)d_in[1];
    const float* leak = (const float*)d_in[2];
    const float* hw   = (const float*)d_in[3];
    const float* hb   = (const float*)d_in[4];
    const float* rw1  = (const float*)d_in[5];
    const float* rb1  = (const float*)d_in[6];
    const float* rw2  = (const float*)d_in[7];
    const float* rb2  = (const float*)d_in[8];
    const float* iw   = (const float*)d_in[9];
    const float* ib   = (const float*)d_in[10];

    float* out = (float*)d_out;
    float* out_img = out;
    float* embs    = out + 98304;
    float* out_raw = out + 98304 + (size_t)17 * 4194304;

    float *kall, *c1, *c2;
    __nv_bfloat16 *ph, *pl, *h1h, *h1l, *h2h, *h2l;
    __nv_bfloat16 *w1h, *w1l, *w2h, *w2l, *w3h, *w3l;
    cudaGetSymbolAddress((void**)&kall, g_kall);
    cudaGetSymbolAddress((void**)&ph,  g_ph);  cudaGetSymbolAddress((void**)&pl,  g_pl);
    cudaGetSymbolAddress((void**)&h1h, g_h1h); cudaGetSymbolAddress((void**)&h1l, g_h1l);
    cudaGetSymbolAddress((void**)&h2h, g_h2h); cudaGetSymbolAddress((void**)&h2l, g_h2l);
    cudaGetSymbolAddress((void**)&w1h, g_w1h); cudaGetSymbolAddress((void**)&w1l, g_w1l);
    cudaGetSymbolAddress((void**)&w2h, g_w2h); cudaGetSymbolAddress((void**)&w2l, g_w2l);
    cudaGetSymbolAddress((void**)&w3h, g_w3h); cudaGetSymbolAddress((void**)&w3l, g_w3l);
    cudaGetSymbolAddress((void**)&c1, g_c1);
    cudaGetSymbolAddress((void**)&c2, g_c2);

    // MBLKS=1: 3 stages x (2*128*40 + 2*32*136) elems * 2B = 113664
    // MBLKS=2: 2 stages x (2*256*40 + 2*32*72)  elems * 2B = 100352
    const int SM1 = 113664;
    const int SM2 = 100352;
    cudaFuncSetAttribute(gemm_wmma<1>, cudaFuncAttributeMaxDynamicSharedMemorySize, SM1);
    cudaFuncSetAttribute(gemm_wmma<2>, cudaFuncAttributeMaxDynamicSharedMemorySize, SM2);

    hyper_kernel<<<KT / 256, 256>>>(lat, hw, hb, kall);
    cudaMemcpyAsync(embs, ca, (size_t)4194304 * sizeof(float), cudaMemcpyDeviceToDevice);

    for (int t = 0; t < NCALLS; t++) {
        float* x  = embs + (size_t)t * 4194304;
        float* xn = x + 4194304;

        build_p_kernel<<<dim3(NF, NB), 256>>>(x, ph, pl);
        gemm_wmma<1><<<dim3(32, NB), 256, SM1>>>(
            w1h, w1l, 384, ph, pl, 384, nullptr, nullptr,
            kall, OFF_BIN, 0, nullptr, h1h, h1l, nullptr, nullptr);
        gemm_wmma<1><<<dim3(32, NB), 256, SM1>>>(
            w2h, w2l, 128, h1h, h1l, 128, nullptr, nullptr,
            kall, OFF_BMID, 0, nullptr, h2h, h2l, nullptr, nullptr);
        gemm_wmma<2><<<dim3(64, NB), 256, SM2>>>(
            w3h, w3l, 512, h2h, h2l, 128, ph, pl,
            kall, OFF_BOUT, OFF_BSH, xn, nullptr, nullptr, x, leak);
    }

    float* xf = embs + (size_t)NCALLS * 4194304;
    conv3x3_kernel<<<dim3(16, 4, NB), 256>>>(xf, rw1, rb1, nullptr, c1, 1);
    conv3x3_kernel<<<dim3(16, 4, NB), 256>>>(c1, rw2, rb2, xf, c2, 0);
    conv_img_kernel<<<dim3(16, NB), 256>>>(c2, iw, ib, out_img, out_raw);
}

// round 10
// speedup vs baseline: 1.1092x; 1.0745x over previous
#include <cuda_runtime.h>
#include <cuda_bf16.h>
#include <mma.h>
#include <math.h>

using namespace nvcuda;

#define NB 8
#define NF 128
#define LATD 256
#define NPIX 4096
#define NCALLS 16
#define FIN 384
#define KT 197376

#define OFF_WIN  0
#define OFF_BIN  49152
#define OFF_WMID 49280
#define OFF_BMID 65664
#define OFF_WOUT 65792
#define OFF_BOUT 98560
#define OFF_WSH  98816
#define OFF_BSH  197120

#define COLSZ 4718592   // 1152 * 4096 (per-batch im2col extent; NOT a power of 2)

// -------- scratch --------
__device__ __align__(16) float g_kall[NB * KT];
__device__ __align__(16) __nv_bfloat16 g_ph[NB * FIN * NPIX], g_pl[NB * FIN * NPIX];
__device__ __align__(16) __nv_bfloat16 g_h1h[NB * NF * NPIX], g_h1l[NB * NF * NPIX];
__device__ __align__(16) __nv_bfloat16 g_h2h[NB * NF * NPIX], g_h2l[NB * NF * NPIX];
__device__ __align__(16) __nv_bfloat16 g_w1h[NB * 128 * 384], g_w1l[NB * 128 * 384];
__device__ __align__(16) __nv_bfloat16 g_w2h[NB * 128 * 128], g_w2l[NB * 128 * 128];
__device__ __align__(16) __nv_bfloat16 g_w3h[NB * 256 * 512], g_w3l[NB * 256 * 512];
__device__ __align__(16) __nv_bfloat16 g_colh[NB * 1152 * NPIX], g_coll[NB * 1152 * NPIX];
__device__ __align__(16) __nv_bfloat16 g_rw1h[NB * 147456], g_rw1l[NB * 147456];
__device__ __align__(16) __nv_bfloat16 g_rw2h[NB * 147456], g_rw2l[NB * 147456];
__device__ __align__(16) float g_c2[NB * NF * NPIX];

#define CP16(dst, src) \
    asm volatile("cp.async.cg.shared.global [%0], [%1], 16;\n" :: "r"(dst), "l"(src))
#define CP_COMMIT() asm volatile("cp.async.commit_group;\n" ::: "memory")
#define CP_WAIT(n)  asm volatile("cp.async.wait_group %0;\n" :: "n"(n) : "memory")

__device__ __forceinline__ void split1(float v, __nv_bfloat16& h, __nv_bfloat16& l) {
    unsigned iv = __float_as_uint(v) & 0xFFFF0000u;
    h = __ushort_as_bfloat16((unsigned short)(iv >> 16));
    l = __float2bfloat16(v - __uint_as_float(iv));
}

// ======================================================================
// hyper + pack fused
// ======================================================================
__global__ void __launch_bounds__(256) hyper_kernel(
    const float* __restrict__ lat, const float* __restrict__ hw,
    const float* __restrict__ hb, float* __restrict__ kall)
{
    __shared__ float ls[NB * LATD];
    const int tid = threadIdx.x;
    for (int i = tid; i < NB * LATD; i += 256) ls[i] = lat[i];
    __syncthreads();
    const int n = blockIdx.x * 256 + tid;
    float acc[NB];
#pragma unroll
    for (int b = 0; b < NB; b++) acc[b] = 0.f;
    for (int k = 0; k < LATD; k++) {
        float w = hw[(size_t)k * KT + n];
#pragma unroll
        for (int b = 0; b < NB; b++) acc[b] = fmaf(ls[b * LATD + k], w, acc[b]);
    }
    const float bias = hb[n];

    float s = 1.f;
    int kind;           // 0=w1, 1=w2, 2=w3, 3=bias
    size_t widx = 0;
    if (n < OFF_BIN)       { s = 0.05103103630798288f; kind = 0; widx = n; }
    else if (n < OFF_WMID) { kind = 3; }
    else if (n < OFF_BMID) { s = 0.08838834764831845f; kind = 1; widx = n - OFF_WMID; }
    else if (n < OFF_WOUT) { kind = 3; }
    else if (n < OFF_BOUT) {
        s = 0.08838834764831845f; kind = 2;
        int i = n - OFF_WOUT;
        widx = (size_t)(i >> 7) * 512 + (i & 127);
    } else if (n < OFF_WSH) { kind = 3; }
    else if (n < OFF_BSH) {
        s = 0.05103103630798288f; kind = 2;
        int i = n - OFF_WSH;
        widx = (size_t)(i / 384) * 512 + 128 + (i % 384);
    } else kind = 3;

#pragma unroll
    for (int b = 0; b < NB; b++) {
        float v = (acc[b] + bias) * s;
        if (kind == 3) {
            kall[(size_t)b * KT + n] = v;
        } else {
            __nv_bfloat16 h, l;
            split1(v, h, l);
            if (kind == 0)      { g_w1h[(size_t)b * 49152 + widx] = h;  g_w1l[(size_t)b * 49152 + widx] = l; }
            else if (kind == 1) { g_w2h[(size_t)b * 16384 + widx] = h;  g_w2l[(size_t)b * 16384 + widx] = l; }
            else                { g_w3h[(size_t)b * 131072 + widx] = h; g_w3l[(size_t)b * 131072 + widx] = l; }
        }
    }
}

// ======================================================================
// pack res-conv weights: [o][c][3][3] -> [o][tap*128+c] hi/lo, replicated 8x
// ======================================================================
__global__ void __launch_bounds__(256) pack_rw_kernel(
    const float* __restrict__ w, __nv_bfloat16* __restrict__ dh,
    __nv_bfloat16* __restrict__ dl)
{
    const int idx = blockIdx.x * 256 + threadIdx.x;   // < 147456
    const int o = idx / 1152, r = idx - o * 1152;
    const int t = r >> 7, c = r & 127;
    float v = w[o * 1152 + c * 9 + t];
    __nv_bfloat16 h, l;
    split1(v, h, l);
#pragma unroll
    for (int b = 0; b < NB; b++) {
        dh[(size_t)b * 147456 + idx] = h;
        dl[(size_t)b * 147456 + idx] = l;
    }
}

// ======================================================================
// im2col (9-tap shifted, zero padded). idx over NB*1152*NPIX.
// ======================================================================
__global__ void __launch_bounds__(256) im2col_f32_kernel(
    const float* __restrict__ src, __nv_bfloat16* __restrict__ dh,
    __nv_bfloat16* __restrict__ dl)
{
    const size_t idx = (size_t)blockIdx.x * 256 + threadIdx.x;
    const int b = (int)(idx / COLSZ);              // true division (COLSZ != 2^k)
    const size_t r = idx - (size_t)b * COLSZ;
    const int k = (int)(r >> 12), px = (int)(r & 4095);
    const int tap = k >> 7, ch = k & 127;
    const int dy = tap / 3 - 1, dx = tap % 3 - 1;
    const int y = (px >> 6) + dy, x = (px & 63) + dx;
    float v = 0.f;
    if ((unsigned)y < 64u && (unsigned)x < 64u)
        v = src[(((size_t)b * 128 + ch) << 12) + y * 64 + x];
    __nv_bfloat16 h, l;
    split1(v, h, l);
    dh[idx] = h; dl[idx] = l;
}

__global__ void __launch_bounds__(256) im2col_bf16_kernel(
    const __nv_bfloat16* __restrict__ sh, const __nv_bfloat16* __restrict__ sl,
    __nv_bfloat16* __restrict__ dh, __nv_bfloat16* __restrict__ dl)
{
    const size_t idx = (size_t)blockIdx.x * 256 + threadIdx.x;
    const int b = (int)(idx / COLSZ);
    const size_t r = idx - (size_t)b * COLSZ;
    const int k = (int)(r >> 12), px = (int)(r & 4095);
    const int tap = k >> 7, ch = k & 127;
    const int dy = tap / 3 - 1, dx = tap % 3 - 1;
    const int y = (px >> 6) + dy, x = (px & 63) + dx;
    __nv_bfloat16 h = __float2bfloat16(0.f), l = h;
    if ((unsigned)y < 64u && (unsigned)x < 64u) {
        size_t s = (((size_t)b * 128 + ch) << 12) + y * 64 + x;
        h = sh[s]; l = sl[s];
    }
    dh[idx] = h; dl[idx] = l;
}

// ======================================================================
// build_p -> hi/lo bf16 planes
// ======================================================================
__global__ void __launch_bounds__(256) build_p_kernel(
    const float* __restrict__ X, __nv_bfloat16* __restrict__ Ph,
    __nv_bfloat16* __restrict__ Pl)
{
    const int c = blockIdx.x, b = blockIdx.y, tid = threadIdx.x;
    __shared__ float sp[68 * 68];
    __shared__ float red[8][6];
    __shared__ float stats[6];
    for (int i = tid; i < 68 * 68; i += 256) sp[i] = 0.f;
    __syncthreads();
    const float* Xp = X + ((size_t)b * NF + c) * NPIX;
    for (int i = tid; i < NPIX; i += 256) {
        int y = i >> 6, x = i & 63;
        sp[(y + 2) * 68 + (x + 2)] = Xp[i];
    }
    __syncthreads();
    const float C = 0.70710678118654752f;
    float vx[16], vsx[16], vsy[16];
    float s0 = 0.f, q0 = 0.f, s1 = 0.f, q1 = 0.f, s2 = 0.f, q2 = 0.f;
#pragma unroll
    for (int it = 0; it < 16; it++) {
        int pix = tid + it * 256;
        int y = pix >> 6, x = pix & 63;
        const float* B = &sp[y * 68 + x];
        float xv = B[2*68+2];
        float sx = C*(B[1*68+4]-B[1*68+0]) + 0.5f*(B[1*68+3]-B[1*68+1])
                 + (B[2*68+4]-B[2*68+0]) + C*(B[2*68+3]-B[2*68+1])
                 + C*(B[3*68+4]-B[3*68+0]) + 0.5f*(B[3*68+3]-B[3*68+1]);
        float sy = C*(B[4*68+1]-B[0*68+1]) + (B[4*68+2]-B[0*68+2])
                 + C*(B[4*68+3]-B[0*68+3])
                 + 0.5f*(B[3*68+1]-B[1*68+1]) + C*(B[3*68+2]-B[1*68+2])
                 + 0.5f*(B[3*68+3]-B[1*68+3]);
        vx[it] = xv; vsx[it] = sx; vsy[it] = sy;
        s0 += xv; q0 = fmaf(xv, xv, q0);
        s1 += sx; q1 = fmaf(sx, sx, q1);
        s2 += sy; q2 = fmaf(sy, sy, q2);
    }
#pragma unroll
    for (int off = 16; off; off >>= 1) {
        s0 += __shfl_down_sync(~0u, s0, off); q0 += __shfl_down_sync(~0u, q0, off);
        s1 += __shfl_down_sync(~0u, s1, off); q1 += __shfl_down_sync(~0u, q1, off);
        s2 += __shfl_down_sync(~0u, s2, off); q2 += __shfl_down_sync(~0u, q2, off);
    }
    if ((tid & 31) == 0) {
        int w = tid >> 5;
        red[w][0]=s0; red[w][1]=q0; red[w][2]=s1; red[w][3]=q1; red[w][4]=s2; red[w][5]=q2;
    }
    __syncthreads();
    if (tid == 0) {
        float S[6] = {0,0,0,0,0,0};
        for (int w = 0; w < 8; w++) for (int j = 0; j < 6; j++) S[j] += red[w][j];
        const float invN = 1.f / 4096.f;
#pragma unroll
        for (int t3 = 0; t3 < 3; t3++) {
            float mu = S[2*t3] * invN;
            float var = fmaxf(S[2*t3+1] * invN - mu*mu, 0.f);
            stats[2*t3] = mu; stats[2*t3+1] = rsqrtf(var + 1e-5f);
        }
    }
    __syncthreads();
    const float mu0 = stats[0], in0 = stats[1], mu1 = stats[2], in1 = stats[3],
                mu2 = stats[4], in2 = stats[5];
    const size_t p0 = ((size_t)b * FIN + c) * NPIX;
#pragma unroll
    for (int it = 0; it < 16; it++) {
        int pix = tid + it * 256;
        float v0 = (vx[it]  - mu0) * in0;
        float v1 = (vsx[it] - mu1) * in1;
        float v2 = (vsy[it] - mu2) * in2;
        __nv_bfloat16 h, l;
        split1(v0, h, l); Ph[p0 + pix] = h; Pl[p0 + pix] = l;
        split1(v1, h, l); Ph[p0 + (size_t)NF*NPIX + pix] = h;   Pl[p0 + (size_t)NF*NPIX + pix] = l;
        split1(v2, h, l); Ph[p0 + (size_t)2*NF*NPIX + pix] = h; Pl[p0 + (size_t)2*NF*NPIX + pix] = l;
    }
}

// ======================================================================
// wmma bf16 GEMM, hi/lo 3-term, cp.async 3-stage / 1 sync per chunk.
// MBLKS=1 (KCH=32): bf16-out => relu+split; fp32-out => bias (+residual)
// MBLKS=2 (KCH=16): gated state update
// ======================================================================
template<int MBLKS>
__global__ void __launch_bounds__(256, 2) gemm_wmma(
    const __nv_bfloat16* __restrict__ Wh, const __nv_bfloat16* __restrict__ Wl,
    int Ktot,
    const __nv_bfloat16* __restrict__ B1h, const __nv_bfloat16* __restrict__ B1l,
    int K1,
    const __nv_bfloat16* __restrict__ B2h, const __nv_bfloat16* __restrict__ B2l,
    const float* __restrict__ kall, int boff1, int boff2,
    const float* __restrict__ bias_dir,
    float* __restrict__ outf,
    __nv_bfloat16* __restrict__ outh, __nv_bfloat16* __restrict__ outl,
    const float* __restrict__ xold, const float* __restrict__ leakp)
{
    constexpr int MT = MBLKS * 128;
    constexpr int NT = 128 / MBLKS;
    constexpr int KCH = (MBLKS == 1) ? 32 : 16;
    constexpr int KK = KCH / 16;
    constexpr int AP = KCH / 8;                  // 16B pieces per A row
    constexpr int AW = KCH + 8;                  // 80B / 48B rows (16B-mult)
    constexpr int BW = (MBLKS == 1) ? 136 : 72;  // 272B / 144B rows (16B-mult)
    constexpr int EW = NT + 4;
    constexpr int BUFE = 2 * MT * AW + 2 * KCH * BW;

    extern __shared__ __align__(16) char sm[];
    __nv_bfloat16* smB = (__nv_bfloat16*)sm;
    float* Es = (float*)sm;

    const int tid = threadIdx.x;
    const int b = blockIdx.y;
    const int n0 = blockIdx.x * NT;
    const int wid = tid >> 5;
    const int wm = (MBLKS == 1) ? (wid >> 1) : wid;
    const int wn = (MBLKS == 1) ? (wid & 1) : 0;

    const __nv_bfloat16* WhB = Wh + (size_t)b * MT * Ktot;
    const __nv_bfloat16* WlB = Wl + (size_t)b * MT * Ktot;

    wmma::fragment<wmma::accumulator, 16, 16, 16, float> acc[2][4];
#pragma unroll
    for (int i = 0; i < 2; i++)
#pragma unroll
        for (int j = 0; j < 4; j++) wmma::fill_fragment(acc[i][j], 0.f);

    auto stage = [&](int kc, int s) {
        __nv_bfloat16* Ahd = smB + (size_t)s * BUFE;
        __nv_bfloat16* Ald = Ahd + MT * AW;
        __nv_bfloat16* Bhd = Ald + MT * AW;
        __nv_bfloat16* Bld = Bhd + KCH * BW;
#pragma unroll
        for (int i = tid; i < MT * AP * 2; i += 256) {
            int plane = (i >= MT * AP);
            int rem = i - plane * MT * AP;
            int m = rem / AP, q = rem - m * AP;
            const __nv_bfloat16* src = (plane ? WlB : WhB) + (size_t)m * Ktot + kc + q * 8;
            unsigned d = (unsigned)__cvta_generic_to_shared(
                (plane ? Ald : Ahd) + m * AW + q * 8);
            CP16(d, src);
        }
        const __nv_bfloat16 *sh, *sl; int ch0;
        if (kc < K1) {
            sh = B1h + (size_t)b * K1 * NPIX; sl = B1l + (size_t)b * K1 * NPIX; ch0 = kc;
        } else {
            int K2 = Ktot - K1;
            sh = B2h + (size_t)b * K2 * NPIX; sl = B2l + (size_t)b * K2 * NPIX; ch0 = kc - K1;
        }
        constexpr int NC8 = NT / 8;
#pragma unroll
        for (int i = tid; i < KCH * NC8 * 2; i += 256) {
            int plane = (i >= KCH * NC8);
            int rem = i - plane * KCH * NC8;
            int k = rem / NC8, c = (rem - k * NC8) * 8;
            const __nv_bfloat16* src = (plane ? sl : sh) + (size_t)(ch0 + k) * NPIX + n0 + c;
            unsigned d = (unsigned)__cvta_generic_to_shared(
                (plane ? Bld : Bhd) + k * BW + c);
            CP16(d, src);
        }
        CP_COMMIT();
    };

    auto compute = [&](int s) {
        const __nv_bfloat16* Ahd = smB + (size_t)s * BUFE;
        const __nv_bfloat16* Ald = Ahd + MT * AW;
        const __nv_bfloat16* Bhd = Ald + MT * AW;
        const __nv_bfloat16* Bld = Bhd + KCH * BW;
#pragma unroll
        for (int kk = 0; kk < KK; kk++) {
            wmma::fragment<wmma::matrix_a, 16, 16, 16, __nv_bfloat16, wmma::row_major> ah[2], al[2];
            wmma::fragment<wmma::matrix_b, 16, 16, 16, __nv_bfloat16, wmma::row_major> bh[4], bl[4];
#pragma unroll
            for (int i = 0; i < 2; i++) {
                wmma::load_matrix_sync(ah[i], Ahd + (wm * 32 + i * 16) * AW + kk * 16, AW);
                wmma::load_matrix_sync(al[i], Ald + (wm * 32 + i * 16) * AW + kk * 16, AW);
            }
#pragma unroll
            for (int j = 0; j < 4; j++) {
                wmma::load_matrix_sync(bh[j], Bhd + kk * 16 * BW + wn * 64 + j * 16, BW);
                wmma::load_matrix_sync(bl[j], Bld + kk * 16 * BW + wn * 64 + j * 16, BW);
            }
#pragma unroll
            for (int i = 0; i < 2; i++)
#pragma unroll
                for (int j = 0; j < 4; j++) {
                    wmma::mma_sync(acc[i][j], ah[i], bh[j], acc[i][j]);
                    wmma::mma_sync(acc[i][j], ah[i], bl[j], acc[i][j]);
                    wmma::mma_sync(acc[i][j], al[i], bh[j], acc[i][j]);
                }
        }
    };

    const int nch = Ktot / KCH;
    stage(0, 0);
    stage(KCH, 1);
    CP_WAIT(1);
    __syncthreads();
    for (int ic = 0; ic < nch; ic++) {
        compute(ic % 3);
        if (ic + 2 < nch) {
            stage((ic + 2) * KCH, (ic + 2) % 3);
            CP_WAIT(1);
        } else {
            CP_WAIT(0);
        }
        __syncthreads();
    }

#pragma unroll
    for (int i = 0; i < 2; i++)
#pragma unroll
        for (int j = 0; j < 4; j++)
            wmma::store_matrix_sync(Es + (wm * 32 + i * 16) * EW + wn * 64 + j * 16,
                                    acc[i][j], EW, wmma::mem_row_major);
    __syncthreads();

    const int m = tid >> 1, seg = tid & 1;
    if (MBLKS == 1) {
        const float bias = kall ? kall[(size_t)b * KT + boff1 + m] : bias_dir[m];
        const size_t base = ((size_t)b * 128 + m) * NPIX + n0 + seg * 64;
        const float* er = Es + m * EW + seg * 64;
        if (outh) {
#pragma unroll
            for (int c = 0; c < 64; c += 2) {
                float v0 = fmaxf(er[c + 0] + bias, 0.f);
                float v1 = fmaxf(er[c + 1] + bias, 0.f);
                __nv_bfloat16 h0, l0, h1, l1;
                split1(v0, h0, l0);
                split1(v1, h1, l1);
                __nv_bfloat162 hp; hp.x = h0; hp.y = h1;
                __nv_bfloat162 lp; lp.x = l0; lp.y = l1;
                *reinterpret_cast<__nv_bfloat162*>(&outh[base + c]) = hp;
                *reinterpret_cast<__nv_bfloat162*>(&outl[base + c]) = lp;
            }
        } else {
#pragma unroll
            for (int c = 0; c < 64; c += 4) {
                float4 o;
                o.x = er[c+0] + bias; o.y = er[c+1] + bias;
                o.z = er[c+2] + bias; o.w = er[c+3] + bias;
                if (xold) {
                    float4 x = *reinterpret_cast<const float4*>(&xold[base + c]);
                    o.x += x.x; o.y += x.y; o.z += x.z; o.w += x.w;
                }
                *reinterpret_cast<float4*>(&outf[base + c]) = o;
            }
        }
    } else {
        const float leak = fminf(fmaxf(leakp[0], 0.001f), 1000.f);
        const float* ka = kall + (size_t)b * KT;
        const float bv = ka[boff1 + m] + ka[boff2 + m];
        const float bg = ka[boff1 + 128 + m] + ka[boff2 + 128 + m];
        const size_t base = ((size_t)b * 128 + m) * NPIX + n0 + seg * 32;
        const float* ev = Es + m * EW + seg * 32;
        const float* eg = Es + (m + 128) * EW + seg * 32;
#pragma unroll
        for (int c = 0; c < 32; c += 4) {
            float4 x = *reinterpret_cast<const float4*>(&xold[base + c]);
            float4 o;
            { float v = ev[c+0] + bv, g = eg[c+0] + bg; o.x = x.x + leak * v / (1.f + __expf(-g)); }
            { float v = ev[c+1] + bv, g = eg[c+1] + bg; o.y = x.y + leak * v / (1.f + __expf(-g)); }
            { float v = ev[c+2] + bv, g = eg[c+2] + bg; o.z = x.z + leak * v / (1.f + __expf(-g)); }
            { float v = ev[c+3] + bv, g = eg[c+3] + bg; o.w = x.w + leak * v / (1.f + __expf(-g)); }
            *reinterpret_cast<float4*>(&outf[base + c]) = o;
        }
    }
}

// ======================================================================
// final 128->3 conv + clip (fp32, small)
// ======================================================================
__global__ void __launch_bounds__(256) conv_img_kernel(
    const float* __restrict__ X, const float* __restrict__ W,
    const float* __restrict__ bias,
    float* __restrict__ out_img, float* __restrict__ out_raw)
{
    const int b = blockIdx.y, y0 = blockIdx.x * 4, tid = threadIdx.x;
    const int r = tid >> 6, x = tid & 63;
    __shared__ float sW[3 * 1152];
    __shared__ float sIn[6][66];
    for (int i = tid; i < 3 * 1152; i += 256) sW[i] = W[i];
    float acc[3] = {0.f, 0.f, 0.f};
    const float* Xb = X + (size_t)b * NF * NPIX;
    for (int ci = 0; ci < NF; ci++) {
        __syncthreads();
        for (int i = tid; i < 6 * 66; i += 256) {
            int ry = i / 66, cx = i - ry * 66;
            int gy = y0 - 1 + ry, gx = cx - 1;
            float v = 0.f;
            if ((unsigned)gy < 64u && (unsigned)gx < 64u)
                v = Xb[(size_t)ci * NPIX + gy * 64 + gx];
            sIn[ry][cx] = v;
        }
        __syncthreads();
        float in[9];
#pragma unroll
        for (int dy = 0; dy < 3; dy++)
#pragma unroll
            for (int dx = 0; dx < 3; dx++) in[dy * 3 + dx] = sIn[r + dy][x + dx];
#pragma unroll
        for (int o = 0; o < 3; o++)
#pragma unroll
            for (int j = 0; j < 9; j++)
                acc[o] = fmaf(in[j], sW[o * 1152 + ci * 9 + j], acc[o]);
    }
#pragma unroll
    for (int o = 0; o < 3; o++) {
        float v = acc[o] + bias[o];
        size_t idx = ((size_t)b * 3 + o) * NPIX + (size_t)(y0 + r) * 64 + x;
        out_raw[idx] = v;
        out_img[idx] = fminf(fmaxf(v, -1.f), 1.f);
    }
}

// ======================================================================
extern "C" void kernel_launch(void* const* d_in, const int* in_sizes, int n_in,
                              void* d_out, int out_size)
{
    const float* lat  = (const float*)d_in[0];
    const float* ca   = (const float*)d_in[1];
    const float* leak = (const float*)d_in[2];
    const float* hw   = (const float*)d_in[3];
    const float* hb   = (const float*)d_in[4];
    const float* rw1  = (const float*)d_in[5];
    const float* rb1  = (const float*)d_in[6];
    const float* rw2  = (const float*)d_in[7];
    const float* rb2  = (const float*)d_in[8];
    const float* iw   = (const float*)d_in[9];
    const float* ib   = (const float*)d_in[10];

    float* out = (float*)d_out;
    float* out_img = out;
    float* embs    = out + 98304;
    float* out_raw = out + 98304 + (size_t)17 * 4194304;

    float *kall, *c2;
    __nv_bfloat16 *ph, *pl, *h1h, *h1l, *h2h, *h2l;
    __nv_bfloat16 *w1h, *w1l, *w2h, *w2l, *w3h, *w3l;
    __nv_bfloat16 *colh, *coll, *r1h, *r1l, *r2h, *r2l;
    cudaGetSymbolAddress((void**)&kall, g_kall);
    cudaGetSymbolAddress((void**)&ph,  g_ph);  cudaGetSymbolAddress((void**)&pl,  g_pl);
    cudaGetSymbolAddress((void**)&h1h, g_h1h); cudaGetSymbolAddress((void**)&h1l, g_h1l);
    cudaGetSymbolAddress((void**)&h2h, g_h2h); cudaGetSymbolAddress((void**)&h2l, g_h2l);
    cudaGetSymbolAddress((void**)&w1h, g_w1h); cudaGetSymbolAddress((void**)&w1l, g_w1l);
    cudaGetSymbolAddress((void**)&w2h, g_w2h); cudaGetSymbolAddress((void**)&w2l, g_w2l);
    cudaGetSymbolAddress((void**)&w3h, g_w3h); cudaGetSymbolAddress((void**)&w3l, g_w3l);
    cudaGetSymbolAddress((void**)&colh, g_colh); cudaGetSymbolAddress((void**)&coll, g_coll);
    cudaGetSymbolAddress((void**)&r1h, g_rw1h); cudaGetSymbolAddress((void**)&r1l, g_rw1l);
    cudaGetSymbolAddress((void**)&r2h, g_rw2h); cudaGetSymbolAddress((void**)&r2l, g_rw2l);
    cudaGetSymbolAddress((void**)&c2, g_c2);

    // uniform smem request -> no carveout reconfig between launches
    const int SM_ALL = 113664;
    cudaFuncSetAttribute(gemm_wmma<1>, cudaFuncAttributeMaxDynamicSharedMemorySize, SM_ALL);
    cudaFuncSetAttribute(gemm_wmma<2>, cudaFuncAttributeMaxDynamicSharedMemorySize, SM_ALL);

    hyper_kernel<<<KT / 256, 256>>>(lat, hw, hb, kall);
    pack_rw_kernel<<<576, 256>>>(rw1, r1h, r1l);
    pack_rw_kernel<<<576, 256>>>(rw2, r2h, r2l);
    cudaMemcpyAsync(embs, ca, (size_t)4194304 * sizeof(float), cudaMemcpyDeviceToDevice);

    for (int t = 0; t < NCALLS; t++) {
        float* x  = embs + (size_t)t * 4194304;
        float* xn = x + 4194304;

        build_p_kernel<<<dim3(NF, NB), 256>>>(x, ph, pl);
        gemm_wmma<1><<<dim3(32, NB), 256, SM_ALL>>>(
            w1h, w1l, 384, ph, pl, 384, nullptr, nullptr,
            kall, OFF_BIN, 0, nullptr, nullptr, h1h, h1l, nullptr, nullptr);
        gemm_wmma<1><<<dim3(32, NB), 256, SM_ALL>>>(
            w2h, w2l, 128, h1h, h1l, 128, nullptr, nullptr,
            kall, OFF_BMID, 0, nullptr, nullptr, h2h, h2l, nullptr, nullptr);
        gemm_wmma<2><<<dim3(64, NB), 256, SM_ALL>>>(
            w3h, w3l, 512, h2h, h2l, 128, ph, pl,
            kall, OFF_BOUT, OFF_BSH, nullptr, xn, nullptr, nullptr, x, leak);
    }

    float* xf = embs + (size_t)NCALLS * 4194304;
    // h = relu(conv3x3(xf, rw1) + rb1)  [tensor-core implicit GEMM, K=1152]
    im2col_f32_kernel<<<147456, 256>>>(xf, colh, coll);
    gemm_wmma<1><<<dim3(32, NB), 256, SM_ALL>>>(
        r1h, r1l, 1152, colh, coll, 1152, nullptr, nullptr,
        nullptr, 0, 0, rb1, nullptr, ph, pl, nullptr, nullptr);
    // y = xf + conv3x3(h, rw2) + rb2
    im2col_bf16_kernel<<<147456, 256>>>(ph, pl, colh, coll);
    gemm_wmma<1><<<dim3(32, NB), 256, SM_ALL>>>(
        r2h, r2l, 1152, colh, coll, 1152, nullptr, nullptr,
        nullptr, 0, 0, rb2, c2, nullptr, nullptr, xf, nullptr);
    conv_img_kernel<<<dim3(16, NB), 256>>>(c2, iw, ib, out_img, out_raw);
}

// round 11
// speedup vs baseline: 1.7912x; 1.6148x over previous
#include <cuda_runtime.h>
#include <cuda_fp16.h>
#include <mma.h>
#include <math.h>

using namespace nvcuda;

#define NB 8
#define NF 128
#define LATD 256
#define NPIX 4096
#define NCALLS 16
#define FIN 384
#define KT 197376

#define OFF_WIN  0
#define OFF_BIN  49152
#define OFF_WMID 49280
#define OFF_BMID 65664
#define OFF_WOUT 65792
#define OFF_BOUT 98560
#define OFF_WSH  98816
#define OFF_BSH  197120

#define COLSZ 4718592   // 1152 * 4096 (NOT a power of 2 — true division!)

// -------- scratch --------
__device__ __align__(16) float g_kall[NB * KT];
__device__ __align__(16) __half g_pf [NB * FIN * NPIX];       // activations: single fp16 plane
__device__ __align__(16) __half g_h1f[NB * NF * NPIX];
__device__ __align__(16) __half g_h2f[NB * NF * NPIX];
__device__ __align__(16) __half g_w1h[NB * 128 * 384], g_w1l[NB * 128 * 384];
__device__ __align__(16) __half g_w2h[NB * 128 * 128], g_w2l[NB * 128 * 128];
__device__ __align__(16) __half g_w3h[NB * 256 * 512], g_w3l[NB * 256 * 512];
__device__ __align__(16) __half g_colf[NB * 1152 * NPIX];
__device__ __align__(16) __half g_rw1h[NB * 147456], g_rw1l[NB * 147456];
__device__ __align__(16) __half g_rw2h[NB * 147456], g_rw2l[NB * 147456];
__device__ __align__(16) float g_c2[NB * NF * NPIX];

#define CP16(dst, src) \
    asm volatile("cp.async.cg.shared.global [%0], [%1], 16;\n" :: "r"(dst), "l"(src))
#define CP_COMMIT() asm volatile("cp.async.commit_group;\n" ::: "memory")
#define CP_WAIT(n)  asm volatile("cp.async.wait_group %0;\n" :: "n"(n) : "memory")

// A-split: w = h + l with fp16 pair (h+l accurate to ~2^-24)
__device__ __forceinline__ void splitA(float v, __half& h, __half& l) {
    h = __float2half_rn(v);
    l = __float2half_rn(v - __half2float(h));
}

// ======================================================================
// hyper + pack fused: bias segs -> kall; weight segs -> fp16 hi/lo planes
// ======================================================================
__global__ void __launch_bounds__(256) hyper_kernel(
    const float* __restrict__ lat, const float* __restrict__ hw,
    const float* __restrict__ hb, float* __restrict__ kall)
{
    __shared__ float ls[NB * LATD];
    const int tid = threadIdx.x;
    for (int i = tid; i < NB * LATD; i += 256) ls[i] = lat[i];
    __syncthreads();
    const int n = blockIdx.x * 256 + tid;
    float acc[NB];
#pragma unroll
    for (int b = 0; b < NB; b++) acc[b] = 0.f;
    for (int k = 0; k < LATD; k++) {
        float w = hw[(size_t)k * KT + n];
#pragma unroll
        for (int b = 0; b < NB; b++) acc[b] = fmaf(ls[b * LATD + k], w, acc[b]);
    }
    const float bias = hb[n];

    float s = 1.f;
    int kind;           // 0=w1, 1=w2, 2=w3, 3=bias
    size_t widx = 0;
    if (n < OFF_BIN)       { s = 0.05103103630798288f; kind = 0; widx = n; }
    else if (n < OFF_WMID) { kind = 3; }
    else if (n < OFF_BMID) { s = 0.08838834764831845f; kind = 1; widx = n - OFF_WMID; }
    else if (n < OFF_WOUT) { kind = 3; }
    else if (n < OFF_BOUT) {
        s = 0.08838834764831845f; kind = 2;
        int i = n - OFF_WOUT;
        widx = (size_t)(i >> 7) * 512 + (i & 127);
    } else if (n < OFF_WSH) { kind = 3; }
    else if (n < OFF_BSH) {
        s = 0.05103103630798288f; kind = 2;
        int i = n - OFF_WSH;
        widx = (size_t)(i / 384) * 512 + 128 + (i % 384);
    } else kind = 3;

#pragma unroll
    for (int b = 0; b < NB; b++) {
        float v = (acc[b] + bias) * s;
        if (kind == 3) {
            kall[(size_t)b * KT + n] = v;
        } else {
            __half h, l;
            splitA(v, h, l);
            if (kind == 0)      { g_w1h[(size_t)b * 49152 + widx] = h;  g_w1l[(size_t)b * 49152 + widx] = l; }
            else if (kind == 1) { g_w2h[(size_t)b * 16384 + widx] = h;  g_w2l[(size_t)b * 16384 + widx] = l; }
            else                { g_w3h[(size_t)b * 131072 + widx] = h; g_w3l[(size_t)b * 131072 + widx] = l; }
        }
    }
}

// ======================================================================
// pack res-conv weights: [o][c][3][3] -> [o][tap*128+c] hi/lo, replicated 8x
// ======================================================================
__global__ void __launch_bounds__(256) pack_rw_kernel(
    const float* __restrict__ w, __half* __restrict__ dh, __half* __restrict__ dl)
{
    const int idx = blockIdx.x * 256 + threadIdx.x;   // < 147456
    const int o = idx / 1152, r = idx - o * 1152;
    const int t = r >> 7, c = r & 127;
    float v = w[o * 1152 + c * 9 + t];
    __half h, l;
    splitA(v, h, l);
#pragma unroll
    for (int b = 0; b < NB; b++) {
        dh[(size_t)b * 147456 + idx] = h;
        dl[(size_t)b * 147456 + idx] = l;
    }
}

// ======================================================================
// im2col (9-tap, zero padded), single fp16 plane out
// ======================================================================
__global__ void __launch_bounds__(256) im2col_f32_kernel(
    const float* __restrict__ src, __half* __restrict__ d)
{
    const size_t idx = (size_t)blockIdx.x * 256 + threadIdx.x;
    const int b = (int)(idx / COLSZ);
    const size_t r = idx - (size_t)b * COLSZ;
    const int k = (int)(r >> 12), px = (int)(r & 4095);
    const int tap = k >> 7, ch = k & 127;
    const int dy = tap / 3 - 1, dx = tap % 3 - 1;
    const int y = (px >> 6) + dy, x = (px & 63) + dx;
    float v = 0.f;
    if ((unsigned)y < 64u && (unsigned)x < 64u)
        v = src[(((size_t)b * 128 + ch) << 12) + y * 64 + x];
    d[idx] = __float2half_rn(v);
}

__global__ void __launch_bounds__(256) im2col_h_kernel(
    const __half* __restrict__ src, __half* __restrict__ d)
{
    const size_t idx = (size_t)blockIdx.x * 256 + threadIdx.x;
    const int b = (int)(idx / COLSZ);
    const size_t r = idx - (size_t)b * COLSZ;
    const int k = (int)(r >> 12), px = (int)(r & 4095);
    const int tap = k >> 7, ch = k & 127;
    const int dy = tap / 3 - 1, dx = tap % 3 - 1;
    const int y = (px >> 6) + dy, x = (px & 63) + dx;
    __half v = __float2half_rn(0.f);
    if ((unsigned)y < 64u && (unsigned)x < 64u)
        v = src[(((size_t)b * 128 + ch) << 12) + y * 64 + x];
    d[idx] = v;
}

// ======================================================================
// build_p -> single fp16 plane
// ======================================================================
__global__ void __launch_bounds__(256) build_p_kernel(
    const float* __restrict__ X, __half* __restrict__ P)
{
    const int c = blockIdx.x, b = blockIdx.y, tid = threadIdx.x;
    __shared__ float sp[68 * 68];
    __shared__ float red[8][6];
    __shared__ float stats[6];
    for (int i = tid; i < 68 * 68; i += 256) sp[i] = 0.f;
    __syncthreads();
    const float* Xp = X + ((size_t)b * NF + c) * NPIX;
    for (int i = tid; i < NPIX; i += 256) {
        int y = i >> 6, x = i & 63;
        sp[(y + 2) * 68 + (x + 2)] = Xp[i];
    }
    __syncthreads();
    const float C = 0.70710678118654752f;
    float vx[16], vsx[16], vsy[16];
    float s0 = 0.f, q0 = 0.f, s1 = 0.f, q1 = 0.f, s2 = 0.f, q2 = 0.f;
#pragma unroll
    for (int it = 0; it < 16; it++) {
        int pix = tid + it * 256;
        int y = pix >> 6, x = pix & 63;
        const float* B = &sp[y * 68 + x];
        float xv = B[2*68+2];
        float sx = C*(B[1*68+4]-B[1*68+0]) + 0.5f*(B[1*68+3]-B[1*68+1])
                 + (B[2*68+4]-B[2*68+0]) + C*(B[2*68+3]-B[2*68+1])
                 + C*(B[3*68+4]-B[3*68+0]) + 0.5f*(B[3*68+3]-B[3*68+1]);
        float sy = C*(B[4*68+1]-B[0*68+1]) + (B[4*68+2]-B[0*68+2])
                 + C*(B[4*68+3]-B[0*68+3])
                 + 0.5f*(B[3*68+1]-B[1*68+1]) + C*(B[3*68+2]-B[1*68+2])
                 + 0.5f*(B[3*68+3]-B[1*68+3]);
        vx[it] = xv; vsx[it] = sx; vsy[it] = sy;
        s0 += xv; q0 = fmaf(xv, xv, q0);
        s1 += sx; q1 = fmaf(sx, sx, q1);
        s2 += sy; q2 = fmaf(sy, sy, q2);
    }
#pragma unroll
    for (int off = 16; off; off >>= 1) {
        s0 += __shfl_down_sync(~0u, s0, off); q0 += __shfl_down_sync(~0u, q0, off);
        s1 += __shfl_down_sync(~0u, s1, off); q1 += __shfl_down_sync(~0u, q1, off);
        s2 += __shfl_down_sync(~0u, s2, off); q2 += __shfl_down_sync(~0u, q2, off);
    }
    if ((tid & 31) == 0) {
        int w = tid >> 5;
        red[w][0]=s0; red[w][1]=q0; red[w][2]=s1; red[w][3]=q1; red[w][4]=s2; red[w][5]=q2;
    }
    __syncthreads();
    if (tid == 0) {
        float S[6] = {0,0,0,0,0,0};
        for (int w = 0; w < 8; w++) for (int j = 0; j < 6; j++) S[j] += red[w][j];
        const float invN = 1.f / 4096.f;
#pragma unroll
        for (int t3 = 0; t3 < 3; t3++) {
            float mu = S[2*t3] * invN;
            float var = fmaxf(S[2*t3+1] * invN - mu*mu, 0.f);
            stats[2*t3] = mu; stats[2*t3+1] = rsqrtf(var + 1e-5f);
        }
    }
    __syncthreads();
    const float mu0 = stats[0], in0 = stats[1], mu1 = stats[2], in1 = stats[3],
                mu2 = stats[4], in2 = stats[5];
    const size_t p0 = ((size_t)b * FIN + c) * NPIX;
#pragma unroll
    for (int it = 0; it < 16; it++) {
        int pix = tid + it * 256;
        P[p0 + pix]                      = __float2half_rn((vx[it]  - mu0) * in0);
        P[p0 + (size_t)NF*NPIX + pix]    = __float2half_rn((vsx[it] - mu1) * in1);
        P[p0 + (size_t)2*NF*NPIX + pix]  = __float2half_rn((vsy[it] - mu2) * in2);
    }
}

// ======================================================================
// wmma fp16 GEMM: D = (Ah+Al) @ B16, 2 MMA terms, 3-stage / 1 sync.
// MBLKS=1 (KCH=32): fp16-out => relu; fp32-out => bias (+residual)
// MBLKS=2 (KCH=16): gated state update
// ======================================================================
template<int MBLKS>
__global__ void __launch_bounds__(256, 2) gemm_wmma(
    const __half* __restrict__ Wh, const __half* __restrict__ Wl,
    int Ktot,
    const __half* __restrict__ B1, int K1, const __half* __restrict__ B2,
    const float* __restrict__ kall, int boff1, int boff2,
    const float* __restrict__ bias_dir,
    float* __restrict__ outf, __half* __restrict__ outh,
    const float* __restrict__ xold, const float* __restrict__ leakp)
{
    constexpr int MT = MBLKS * 128;
    constexpr int NT = 128 / MBLKS;
    constexpr int KCH = (MBLKS == 1) ? 32 : 16;
    constexpr int KK = KCH / 16;
    constexpr int AP = KCH / 8;                  // 16B pieces per A row
    constexpr int AW = KCH + 8;                  // 80B / 48B rows (16B-mult)
    constexpr int BW = (MBLKS == 1) ? 136 : 72;  // 272B / 144B rows (16B-mult)
    constexpr int EW = NT + 4;
    constexpr int BUFE = 2 * MT * AW + KCH * BW; // halfs per stage (B single plane)

    extern __shared__ __align__(16) char sm[];
    __half* smB = (__half*)sm;
    float* Es = (float*)sm;

    const int tid = threadIdx.x;
    const int b = blockIdx.y;
    const int n0 = blockIdx.x * NT;
    const int wid = tid >> 5;
    const int wm = (MBLKS == 1) ? (wid >> 1) : wid;
    const int wn = (MBLKS == 1) ? (wid & 1) : 0;

    const __half* WhB = Wh + (size_t)b * MT * Ktot;
    const __half* WlB = Wl + (size_t)b * MT * Ktot;

    wmma::fragment<wmma::accumulator, 16, 16, 16, float> acc[2][4];
#pragma unroll
    for (int i = 0; i < 2; i++)
#pragma unroll
        for (int j = 0; j < 4; j++) wmma::fill_fragment(acc[i][j], 0.f);

    auto stage = [&](int kc, int s) {
        __half* Ahd = smB + (size_t)s * BUFE;
        __half* Ald = Ahd + MT * AW;
        __half* Bfd = Ald + MT * AW;
#pragma unroll
        for (int i = tid; i < MT * AP * 2; i += 256) {
            int plane = (i >= MT * AP);
            int rem = i - plane * MT * AP;
            int m = rem / AP, q = rem - m * AP;
            const __half* src = (plane ? WlB : WhB) + (size_t)m * Ktot + kc + q * 8;
            unsigned d = (unsigned)__cvta_generic_to_shared(
                (plane ? Ald : Ahd) + m * AW + q * 8);
            CP16(d, src);
        }
        const __half* sf; int ch0;
        if (kc < K1) { sf = B1 + (size_t)b * K1 * NPIX; ch0 = kc; }
        else { sf = B2 + (size_t)b * (Ktot - K1) * NPIX; ch0 = kc - K1; }
        constexpr int NC8 = NT / 8;
#pragma unroll
        for (int i = tid; i < KCH * NC8; i += 256) {
            int k = i / NC8, c = (i - k * NC8) * 8;
            const __half* src = sf + (size_t)(ch0 + k) * NPIX + n0 + c;
            unsigned d = (unsigned)__cvta_generic_to_shared(Bfd + k * BW + c);
            CP16(d, src);
        }
        CP_COMMIT();
    };

    auto compute = [&](int s) {
        const __half* Ahd = smB + (size_t)s * BUFE;
        const __half* Ald = Ahd + MT * AW;
        const __half* Bfd = Ald + MT * AW;
#pragma unroll
        for (int kk = 0; kk < KK; kk++) {
            wmma::fragment<wmma::matrix_a, 16, 16, 16, __half, wmma::row_major> ah[2], al[2];
            wmma::fragment<wmma::matrix_b, 16, 16, 16, __half, wmma::row_major> bf[4];
#pragma unroll
            for (int i = 0; i < 2; i++) {
                wmma::load_matrix_sync(ah[i], Ahd + (wm * 32 + i * 16) * AW + kk * 16, AW);
                wmma::load_matrix_sync(al[i], Ald + (wm * 32 + i * 16) * AW + kk * 16, AW);
            }
#pragma unroll
            for (int j = 0; j < 4; j++)
                wmma::load_matrix_sync(bf[j], Bfd + kk * 16 * BW + wn * 64 + j * 16, BW);
#pragma unroll
            for (int i = 0; i < 2; i++)
#pragma unroll
                for (int j = 0; j < 4; j++) {
                    wmma::mma_sync(acc[i][j], ah[i], bf[j], acc[i][j]);
                    wmma::mma_sync(acc[i][j], al[i], bf[j], acc[i][j]);
                }
        }
    };

    const int nch = Ktot / KCH;
    stage(0, 0);
    stage(KCH, 1);
    CP_WAIT(1);
    __syncthreads();
    for (int ic = 0; ic < nch; ic++) {
        compute(ic % 3);
        if (ic + 2 < nch) {
            stage((ic + 2) * KCH, (ic + 2) % 3);
            CP_WAIT(1);
        } else {
            CP_WAIT(0);
        }
        __syncthreads();
    }

#pragma unroll
    for (int i = 0; i < 2; i++)
#pragma unroll
        for (int j = 0; j < 4; j++)
            wmma::store_matrix_sync(Es + (wm * 32 + i * 16) * EW + wn * 64 + j * 16,
                                    acc[i][j], EW, wmma::mem_row_major);
    __syncthreads();

    const int m = tid >> 1, seg = tid & 1;
    if (MBLKS == 1) {
        const float bias = kall ? kall[(size_t)b * KT + boff1 + m] : bias_dir[m];
        const size_t base = ((size_t)b * 128 + m) * NPIX + n0 + seg * 64;
        const float* er = Es + m * EW + seg * 64;
        if (outh) {
#pragma unroll
            for (int c = 0; c < 64; c += 2) {
                __half2 o;
                o.x = __float2half_rn(fmaxf(er[c + 0] + bias, 0.f));
                o.y = __float2half_rn(fmaxf(er[c + 1] + bias, 0.f));
                *reinterpret_cast<__half2*>(&outh[base + c]) = o;
            }
        } else {
#pragma unroll
            for (int c = 0; c < 64; c += 4) {
                float4 o;
                o.x = er[c+0] + bias; o.y = er[c+1] + bias;
                o.z = er[c+2] + bias; o.w = er[c+3] + bias;
                if (xold) {
                    float4 x = *reinterpret_cast<const float4*>(&xold[base + c]);
                    o.x += x.x; o.y += x.y; o.z += x.z; o.w += x.w;
                }
                *reinterpret_cast<float4*>(&outf[base + c]) = o;
            }
        }
    } else {
        const float leak = fminf(fmaxf(leakp[0], 0.001f), 1000.f);
        const float* ka = kall + (size_t)b * KT;
        const float bv = ka[boff1 + m] + ka[boff2 + m];
        const float bg = ka[boff1 + 128 + m] + ka[boff2 + 128 + m];
        const size_t base = ((size_t)b * 128 + m) * NPIX + n0 + seg * 32;
        const float* ev = Es + m * EW + seg * 32;
        const float* eg = Es + (m + 128) * EW + seg * 32;
#pragma unroll
        for (int c = 0; c < 32; c += 4) {
            float4 x = *reinterpret_cast<const float4*>(&xold[base + c]);
            float4 o;
            { float v = ev[c+0] + bv, g = eg[c+0] + bg; o.x = x.x + leak * v / (1.f + __expf(-g)); }
            { float v = ev[c+1] + bv, g = eg[c+1] + bg; o.y = x.y + leak * v / (1.f + __expf(-g)); }
            { float v = ev[c+2] + bv, g = eg[c+2] + bg; o.z = x.z + leak * v / (1.f + __expf(-g)); }
            { float v = ev[c+3] + bv, g = eg[c+3] + bg; o.w = x.w + leak * v / (1.f + __expf(-g)); }
            *reinterpret_cast<float4*>(&outf[base + c]) = o;
        }
    }
}

// ======================================================================
// final 128->3 conv + clip (fp32, small)
// ======================================================================
__global__ void __launch_bounds__(256) conv_img_kernel(
    const float* __restrict__ X, const float* __restrict__ W,
    const float* __restrict__ bias,
    float* __restrict__ out_img, float* __restrict__ out_raw)
{
    const int b = blockIdx.y, y0 = blockIdx.x * 4, tid = threadIdx.x;
    const int r = tid >> 6, x = tid & 63;
    __shared__ float sW[3 * 1152];
    __shared__ float sIn[6][66];
    for (int i = tid; i < 3 * 1152; i += 256) sW[i] = W[i];
    float acc[3] = {0.f, 0.f, 0.f};
    const float* Xb = X + (size_t)b * NF * NPIX;
    for (int ci = 0; ci < NF; ci++) {
        __syncthreads();
        for (int i = tid; i < 6 * 66; i += 256) {
            int ry = i / 66, cx = i - ry * 66;
            int gy = y0 - 1 + ry, gx = cx - 1;
            float v = 0.f;
            if ((unsigned)gy < 64u && (unsigned)gx < 64u)
                v = Xb[(size_t)ci * NPIX + gy * 64 + gx];
            sIn[ry][cx] = v;
        }
        __syncthreads();
        float in[9];
#pragma unroll
        for (int dy = 0; dy < 3; dy++)
#pragma unroll
            for (int dx = 0; dx < 3; dx++) in[dy * 3 + dx] = sIn[r + dy][x + dx];
#pragma unroll
        for (int o = 0; o < 3; o++)
#pragma unroll
            for (int j = 0; j < 9; j++)
                acc[o] = fmaf(in[j], sW[o * 1152 + ci * 9 + j], acc[o]);
    }
#pragma unroll
    for (int o = 0; o < 3; o++) {
        float v = acc[o] + bias[o];
        size_t idx = ((size_t)b * 3 + o) * NPIX + (size_t)(y0 + r) * 64 + x;
        out_raw[idx] = v;
        out_img[idx] = fminf(fmaxf(v, -1.f), 1.f);
    }
}

// ======================================================================
extern "C" void kernel_launch(void* const* d_in, const int* in_sizes, int n_in,
                              void* d_out, int out_size)
{
    const float* lat  = (const float*)d_in[0];
    const float* ca   = (const float*)d_in[1];
    const float* leak = (const float*)d_in[2];
    const float* hw   = (const float*)d_in[3];
    const float* hb   = (const float*)d_in[4];
    const float* rw1  = (const float*)d_in[5];
    const float* rb1  = (const float*)d_in[6];
    const float* rw2  = (const float*)d_in[7];
    const float* rb2  = (const float*)d_in[8];
    const float* iw   = (const float*)d_in[9];
    const float* ib   = (const float*)d_in[10];

    float* out = (float*)d_out;
    float* out_img = out;
    float* embs    = out + 98304;
    float* out_raw = out + 98304 + (size_t)17 * 4194304;

    float *kall, *c2;
    __half *pf, *h1f, *h2f, *colf;
    __half *w1h, *w1l, *w2h, *w2l, *w3h, *w3l, *r1h, *r1l, *r2h, *r2l;
    cudaGetSymbolAddress((void**)&kall, g_kall);
    cudaGetSymbolAddress((void**)&pf,  g_pf);
    cudaGetSymbolAddress((void**)&h1f, g_h1f);
    cudaGetSymbolAddress((void**)&h2f, g_h2f);
    cudaGetSymbolAddress((void**)&w1h, g_w1h); cudaGetSymbolAddress((void**)&w1l, g_w1l);
    cudaGetSymbolAddress((void**)&w2h, g_w2h); cudaGetSymbolAddress((void**)&w2l, g_w2l);
    cudaGetSymbolAddress((void**)&w3h, g_w3h); cudaGetSymbolAddress((void**)&w3l, g_w3l);
    cudaGetSymbolAddress((void**)&colf, g_colf);
    cudaGetSymbolAddress((void**)&r1h, g_rw1h); cudaGetSymbolAddress((void**)&r1l, g_rw1l);
    cudaGetSymbolAddress((void**)&r2h, g_rw2h); cudaGetSymbolAddress((void**)&r2l, g_rw2l);
    cudaGetSymbolAddress((void**)&c2, g_c2);

    // uniform smem: MBLKS=1 stage = (2*128*40 + 32*136)*2B = 29184; x3 = 87552
    //               MBLKS=2 stage = (2*256*24 + 16*72)*2B  = 26880; x3 = 80640
    const int SM_ALL = 87552;
    cudaFuncSetAttribute(gemm_wmma<1>, cudaFuncAttributeMaxDynamicSharedMemorySize, SM_ALL);
    cudaFuncSetAttribute(gemm_wmma<2>, cudaFuncAttributeMaxDynamicSharedMemorySize, SM_ALL);

    hyper_kernel<<<KT / 256, 256>>>(lat, hw, hb, kall);
    pack_rw_kernel<<<576, 256>>>(rw1, r1h, r1l);
    pack_rw_kernel<<<576, 256>>>(rw2, r2h, r2l);
    cudaMemcpyAsync(embs, ca, (size_t)4194304 * sizeof(float), cudaMemcpyDeviceToDevice);

    for (int t = 0; t < NCALLS; t++) {
        float* x  = embs + (size_t)t * 4194304;
        float* xn = x + 4194304;

        build_p_kernel<<<dim3(NF, NB), 256>>>(x, pf);
        // h1 = relu(W_in @ p + b_in)
        gemm_wmma<1><<<dim3(32, NB), 256, SM_ALL>>>(
            w1h, w1l, 384, pf, 384, nullptr,
            kall, OFF_BIN, 0, nullptr, nullptr, h1f, nullptr, nullptr);
        // h2 = relu(W_mid @ h1 + b_mid)
        gemm_wmma<1><<<dim3(32, NB), 256, SM_ALL>>>(
            w2h, w2l, 128, h1f, 128, nullptr,
            kall, OFF_BMID, 0, nullptr, nullptr, h2f, nullptr, nullptr);
        // dn = W_out@h2 + W_sh@p (+biases); xn = x + leak*val*sigmoid(gate)
        gemm_wmma<2><<<dim3(64, NB), 256, SM_ALL>>>(
            w3h, w3l, 512, h2f, 128, pf,
            kall, OFF_BOUT, OFF_BSH, nullptr, xn, nullptr, x, leak);
    }

    float* xf = embs + (size_t)NCALLS * 4194304;
    // h = relu(conv3x3(xf, rw1) + rb1)  [implicit GEMM, K=1152]
    im2col_f32_kernel<<<147456, 256>>>(xf, colf);
    gemm_wmma<1><<<dim3(32, NB), 256, SM_ALL>>>(
        r1h, r1l, 1152, colf, 1152, nullptr,
        nullptr, 0, 0, rb1, nullptr, pf, nullptr, nullptr);
    // y = xf + conv3x3(h, rw2) + rb2
    im2col_h_kernel<<<147456, 256>>>(pf, colf);
    gemm_wmma<1><<<dim3(32, NB), 256, SM_ALL>>>(
        r2h, r2l, 1152, colf, 1152, nullptr,
        nullptr, 0, 0, rb2, c2, nullptr, xf, nullptr);
    conv_img_kernel<<<dim3(16, NB), 256>>>(c2, iw, ib, out_img, out_raw);
}

// round 12
// speedup vs baseline: 1.8817x; 1.0505x over previous
#include <cuda_runtime.h>
#include <cuda_fp16.h>
#include <mma.h>
#include <math.h>

using namespace nvcuda;

#define NB 8
#define NF 128
#define LATD 256
#define NPIX 4096
#define NCALLS 16
#define FIN 384
#define KT 197376

#define OFF_WIN  0
#define OFF_BIN  49152
#define OFF_WMID 49280
#define OFF_BMID 65664
#define OFF_WOUT 65792
#define OFF_BOUT 98560
#define OFF_WSH  98816
#define OFF_BSH  197120

#define COLSZ 4718592   // 1152 * 4096 (NOT a power of 2 — true division!)

// -------- scratch --------
__device__ __align__(16) float g_kall[NB * KT];
__device__ __align__(16) __half g_pf [NB * FIN * NPIX];
__device__ __align__(16) __half g_h2f[NB * NF * NPIX];
__device__ __align__(16) __half g_w1h[NB * 128 * 384], g_w1l[NB * 128 * 384];
__device__ __align__(16) __half g_w2h[NB * 128 * 128], g_w2l[NB * 128 * 128];
__device__ __align__(16) __half g_w3h[NB * 256 * 512], g_w3l[NB * 256 * 512];
__device__ __align__(16) __half g_colf[NB * 1152 * NPIX];
__device__ __align__(16) __half g_rw1h[NB * 147456], g_rw1l[NB * 147456];
__device__ __align__(16) __half g_rw2h[NB * 147456], g_rw2l[NB * 147456];
__device__ __align__(16) float g_c2[NB * NF * NPIX];

#define CP16(dst, src) \
    asm volatile("cp.async.cg.shared.global [%0], [%1], 16;\n" :: "r"(dst), "l"(src))
#define CP_COMMIT() asm volatile("cp.async.commit_group;\n" ::: "memory")
#define CP_WAIT(n)  asm volatile("cp.async.wait_group %0;\n" :: "n"(n) : "memory")

__device__ __forceinline__ void splitA(float v, __half& h, __half& l) {
    h = __float2half_rn(v);
    l = __float2half_rn(v - __half2float(h));
}

// ======================================================================
// hyper + pack fused
// ======================================================================
__global__ void __launch_bounds__(256) hyper_kernel(
    const float* __restrict__ lat, const float* __restrict__ hw,
    const float* __restrict__ hb, float* __restrict__ kall)
{
    __shared__ float ls[NB * LATD];
    const int tid = threadIdx.x;
    for (int i = tid; i < NB * LATD; i += 256) ls[i] = lat[i];
    __syncthreads();
    const int n = blockIdx.x * 256 + tid;
    float acc[NB];
#pragma unroll
    for (int b = 0; b < NB; b++) acc[b] = 0.f;
    for (int k = 0; k < LATD; k++) {
        float w = hw[(size_t)k * KT + n];
#pragma unroll
        for (int b = 0; b < NB; b++) acc[b] = fmaf(ls[b * LATD + k], w, acc[b]);
    }
    const float bias = hb[n];

    float s = 1.f;
    int kind;
    size_t widx = 0;
    if (n < OFF_BIN)       { s = 0.05103103630798288f; kind = 0; widx = n; }
    else if (n < OFF_WMID) { kind = 3; }
    else if (n < OFF_BMID) { s = 0.08838834764831845f; kind = 1; widx = n - OFF_WMID; }
    else if (n < OFF_WOUT) { kind = 3; }
    else if (n < OFF_BOUT) {
        s = 0.08838834764831845f; kind = 2;
        int i = n - OFF_WOUT;
        widx = (size_t)(i >> 7) * 512 + (i & 127);
    } else if (n < OFF_WSH) { kind = 3; }
    else if (n < OFF_BSH) {
        s = 0.05103103630798288f; kind = 2;
        int i = n - OFF_WSH;
        widx = (size_t)(i / 384) * 512 + 128 + (i % 384);
    } else kind = 3;

#pragma unroll
    for (int b = 0; b < NB; b++) {
        float v = (acc[b] + bias) * s;
        if (kind == 3) {
            kall[(size_t)b * KT + n] = v;
        } else {
            __half h, l;
            splitA(v, h, l);
            if (kind == 0)      { g_w1h[(size_t)b * 49152 + widx] = h;  g_w1l[(size_t)b * 49152 + widx] = l; }
            else if (kind == 1) { g_w2h[(size_t)b * 16384 + widx] = h;  g_w2l[(size_t)b * 16384 + widx] = l; }
            else                { g_w3h[(size_t)b * 131072 + widx] = h; g_w3l[(size_t)b * 131072 + widx] = l; }
        }
    }
}

// ======================================================================
// pack res-conv weights
// ======================================================================
__global__ void __launch_bounds__(256) pack_rw_kernel(
    const float* __restrict__ w, __half* __restrict__ dh, __half* __restrict__ dl)
{
    const int idx = blockIdx.x * 256 + threadIdx.x;
    const int o = idx / 1152, r = idx - o * 1152;
    const int t = r >> 7, c = r & 127;
    float v = w[o * 1152 + c * 9 + t];
    __half h, l;
    splitA(v, h, l);
#pragma unroll
    for (int b = 0; b < NB; b++) {
        dh[(size_t)b * 147456 + idx] = h;
        dl[(size_t)b * 147456 + idx] = l;
    }
}

// ======================================================================
// im2col
// ======================================================================
__global__ void __launch_bounds__(256) im2col_f32_kernel(
    const float* __restrict__ src, __half* __restrict__ d)
{
    const size_t idx = (size_t)blockIdx.x * 256 + threadIdx.x;
    const int b = (int)(idx / COLSZ);
    const size_t r = idx - (size_t)b * COLSZ;
    const int k = (int)(r >> 12), px = (int)(r & 4095);
    const int tap = k >> 7, ch = k & 127;
    const int dy = tap / 3 - 1, dx = tap % 3 - 1;
    const int y = (px >> 6) + dy, x = (px & 63) + dx;
    float v = 0.f;
    if ((unsigned)y < 64u && (unsigned)x < 64u)
        v = src[(((size_t)b * 128 + ch) << 12) + y * 64 + x];
    d[idx] = __float2half_rn(v);
}

__global__ void __launch_bounds__(256) im2col_h_kernel(
    const __half* __restrict__ src, __half* __restrict__ d)
{
    const size_t idx = (size_t)blockIdx.x * 256 + threadIdx.x;
    const int b = (int)(idx / COLSZ);
    const size_t r = idx - (size_t)b * COLSZ;
    const int k = (int)(r >> 12), px = (int)(r & 4095);
    const int tap = k >> 7, ch = k & 127;
    const int dy = tap / 3 - 1, dx = tap % 3 - 1;
    const int y = (px >> 6) + dy, x = (px & 63) + dx;
    __half v = __float2half_rn(0.f);
    if ((unsigned)y < 64u && (unsigned)x < 64u)
        v = src[(((size_t)b * 128 + ch) << 12) + y * 64 + x];
    d[idx] = v;
}

// ======================================================================
// build_p -> single fp16 plane
// ======================================================================
__global__ void __launch_bounds__(256) build_p_kernel(
    const float* __restrict__ X, __half* __restrict__ P)
{
    const int c = blockIdx.x, b = blockIdx.y, tid = threadIdx.x;
    __shared__ float sp[68 * 68];
    __shared__ float red[8][6];
    __shared__ float stats[6];
    for (int i = tid; i < 68 * 68; i += 256) sp[i] = 0.f;
    __syncthreads();
    const float* Xp = X + ((size_t)b * NF + c) * NPIX;
    for (int i = tid; i < NPIX; i += 256) {
        int y = i >> 6, x = i & 63;
        sp[(y + 2) * 68 + (x + 2)] = Xp[i];
    }
    __syncthreads();
    const float C = 0.70710678118654752f;
    float vx[16], vsx[16], vsy[16];
    float s0 = 0.f, q0 = 0.f, s1 = 0.f, q1 = 0.f, s2 = 0.f, q2 = 0.f;
#pragma unroll
    for (int it = 0; it < 16; it++) {
        int pix = tid + it * 256;
        int y = pix >> 6, x = pix & 63;
        const float* B = &sp[y * 68 + x];
        float xv = B[2*68+2];
        float sx = C*(B[1*68+4]-B[1*68+0]) + 0.5f*(B[1*68+3]-B[1*68+1])
                 + (B[2*68+4]-B[2*68+0]) + C*(B[2*68+3]-B[2*68+1])
                 + C*(B[3*68+4]-B[3*68+0]) + 0.5f*(B[3*68+3]-B[3*68+1]);
        float sy = C*(B[4*68+1]-B[0*68+1]) + (B[4*68+2]-B[0*68+2])
                 + C*(B[4*68+3]-B[0*68+3])
                 + 0.5f*(B[3*68+1]-B[1*68+1]) + C*(B[3*68+2]-B[1*68+2])
                 + 0.5f*(B[3*68+3]-B[1*68+3]);
        vx[it] = xv; vsx[it] = sx; vsy[it] = sy;
        s0 += xv; q0 = fmaf(xv, xv, q0);
        s1 += sx; q1 = fmaf(sx, sx, q1);
        s2 += sy; q2 = fmaf(sy, sy, q2);
    }
#pragma unroll
    for (int off = 16; off; off >>= 1) {
        s0 += __shfl_down_sync(~0u, s0, off); q0 += __shfl_down_sync(~0u, q0, off);
        s1 += __shfl_down_sync(~0u, s1, off); q1 += __shfl_down_sync(~0u, q1, off);
        s2 += __shfl_down_sync(~0u, s2, off); q2 += __shfl_down_sync(~0u, q2, off);
    }
    if ((tid & 31) == 0) {
        int w = tid >> 5;
        red[w][0]=s0; red[w][1]=q0; red[w][2]=s1; red[w][3]=q1; red[w][4]=s2; red[w][5]=q2;
    }
    __syncthreads();
    if (tid == 0) {
        float S[6] = {0,0,0,0,0,0};
        for (int w = 0; w < 8; w++) for (int j = 0; j < 6; j++) S[j] += red[w][j];
        const float invN = 1.f / 4096.f;
#pragma unroll
        for (int t3 = 0; t3 < 3; t3++) {
            float mu = S[2*t3] * invN;
            float var = fmaxf(S[2*t3+1] * invN - mu*mu, 0.f);
            stats[2*t3] = mu; stats[2*t3+1] = rsqrtf(var + 1e-5f);
        }
    }
    __syncthreads();
    const float mu0 = stats[0], in0 = stats[1], mu1 = stats[2], in1 = stats[3],
                mu2 = stats[4], in2 = stats[5];
    const size_t p0 = ((size_t)b * FIN + c) * NPIX;
#pragma unroll
    for (int it = 0; it < 16; it++) {
        int pix = tid + it * 256;
        P[p0 + pix]                      = __float2half_rn((vx[it]  - mu0) * in0);
        P[p0 + (size_t)NF*NPIX + pix]    = __float2half_rn((vsx[it] - mu1) * in1);
        P[p0 + (size_t)2*NF*NPIX + pix]  = __float2half_rn((vsy[it] - mu2) * in2);
    }
}

// ======================================================================
// FUSED g1+g2: h2 = relu(W2 @ relu(W1 @ p + b1) + b2), h1 lives in smem.
// CTA tile: 128 channels x 128 pixels. 256 threads.
// smem: [0..49920) phase-1 stage (3x); Es fp32 [0..67584); H fp16 at 69632.
// ======================================================================
__global__ void __launch_bounds__(256, 2) mlp12_kernel(
    const __half* __restrict__ W1h, const __half* __restrict__ W1l,
    const __half* __restrict__ W2h, const __half* __restrict__ W2l,
    const __half* __restrict__ P, const float* __restrict__ kall,
    __half* __restrict__ H2out)
{
    constexpr int KCH = 16;
    constexpr int AW = 24;          // 48B rows
    constexpr int BW = 136;         // 272B rows
    constexpr int EW = 132;
    constexpr int A_ELEMS = 128 * AW;                // 3072 halfs / plane
    constexpr int BUF1 = 2 * A_ELEMS + KCH * BW;     // 8320 halfs / stage
    constexpr int BUF2 = 2 * A_ELEMS;                // 6144 halfs / stage

    extern __shared__ __align__(16) char sm[];
    __half* smH = (__half*)sm;
    float* Es = (float*)sm;
    __half* H = (__half*)(sm + 69632);               // 128 x 136 fp16

    const int tid = threadIdx.x;
    const int b = blockIdx.y;
    const int n0 = blockIdx.x * 128;
    const int wid = tid >> 5;
    const int wm = wid >> 1, wn = wid & 1;

    const __half* W1hB = W1h + (size_t)b * 49152;
    const __half* W1lB = W1l + (size_t)b * 49152;
    const __half* W2hB = W2h + (size_t)b * 16384;
    const __half* W2lB = W2l + (size_t)b * 16384;
    const __half* Pb = P + (size_t)b * FIN * NPIX;

    wmma::fragment<wmma::accumulator, 16, 16, 16, float> acc[2][4];
#pragma unroll
    for (int i = 0; i < 2; i++)
#pragma unroll
        for (int j = 0; j < 4; j++) wmma::fill_fragment(acc[i][j], 0.f);

    // ---------------- phase 1: W1 (Ktot=384), B from global ----------------
    auto stage1 = [&](int kc, int s) {
        __half* Ah = smH + (size_t)s * BUF1;
        __half* Al = Ah + A_ELEMS;
        __half* Bf = Al + A_ELEMS;
#pragma unroll
        for (int i = tid; i < 512; i += 256) {       // 128 rows * 2 pieces * 2 planes
            int plane = (i >= 256);
            int rem = i - plane * 256;
            int m = rem >> 1, q = rem & 1;
            const __half* src = (plane ? W1lB : W1hB) + (size_t)m * 384 + kc + q * 8;
            unsigned d = (unsigned)__cvta_generic_to_shared(
                (plane ? Al : Ah) + m * AW + q * 8);
            CP16(d, src);
        }
        {
            int k = tid >> 4, c = (tid & 15) * 8;    // 16 rows x 16 pieces = 256
            const __half* src = Pb + (size_t)(kc + k) * NPIX + n0 + c;
            unsigned d = (unsigned)__cvta_generic_to_shared(Bf + k * BW + c);
            CP16(d, src);
        }
        CP_COMMIT();
    };
    auto compute1 = [&](int s) {
        const __half* Ah = smH + (size_t)s * BUF1;
        const __half* Al = Ah + A_ELEMS;
        const __half* Bf = Al + A_ELEMS;
        wmma::fragment<wmma::matrix_a, 16, 16, 16, __half, wmma::row_major> ah[2], al[2];
        wmma::fragment<wmma::matrix_b, 16, 16, 16, __half, wmma::row_major> bf[4];
#pragma unroll
        for (int i = 0; i < 2; i++) {
            wmma::load_matrix_sync(ah[i], Ah + (wm * 32 + i * 16) * AW, AW);
            wmma::load_matrix_sync(al[i], Al + (wm * 32 + i * 16) * AW, AW);
        }
#pragma unroll
        for (int j = 0; j < 4; j++)
            wmma::load_matrix_sync(bf[j], Bf + wn * 64 + j * 16, BW);
#pragma unroll
        for (int i = 0; i < 2; i++)
#pragma unroll
            for (int j = 0; j < 4; j++) {
                wmma::mma_sync(acc[i][j], ah[i], bf[j], acc[i][j]);
                wmma::mma_sync(acc[i][j], al[i], bf[j], acc[i][j]);
            }
    };

    {
        const int nch = 384 / KCH;                   // 24
        stage1(0, 0);
        stage1(KCH, 1);
        CP_WAIT(1);
        __syncthreads();
        for (int ic = 0; ic < nch; ic++) {
            compute1(ic % 3);
            if (ic + 2 < nch) {
                stage1((ic + 2) * KCH, (ic + 2) % 3);
                CP_WAIT(1);
            } else {
                CP_WAIT(0);
            }
            __syncthreads();
        }
    }

    // epilogue 1: acc -> Es -> relu+bias -> H (smem fp16, B layout for phase 2)
#pragma unroll
    for (int i = 0; i < 2; i++)
#pragma unroll
        for (int j = 0; j < 4; j++)
            wmma::store_matrix_sync(Es + (wm * 32 + i * 16) * EW + wn * 64 + j * 16,
                                    acc[i][j], EW, wmma::mem_row_major);
    __syncthreads();
    {
        const int m = tid >> 1, seg = tid & 1;
        const float bias1 = kall[(size_t)b * KT + OFF_BIN + m];
        const float* er = Es + m * EW + seg * 64;
        __half* hr = H + m * BW + seg * 64;
#pragma unroll
        for (int c = 0; c < 64; c += 2) {
            __half2 o;
            o.x = __float2half_rn(fmaxf(er[c + 0] + bias1, 0.f));
            o.y = __float2half_rn(fmaxf(er[c + 1] + bias1, 0.f));
            *reinterpret_cast<__half2*>(&hr[c]) = o;
        }
    }
    __syncthreads();

    // ---------------- phase 2: W2 (Ktot=128), B from smem H ----------------
#pragma unroll
    for (int i = 0; i < 2; i++)
#pragma unroll
        for (int j = 0; j < 4; j++) wmma::fill_fragment(acc[i][j], 0.f);

    auto stage2 = [&](int kc, int s) {
        __half* Ah = smH + (size_t)s * BUF2;
        __half* Al = Ah + A_ELEMS;
#pragma unroll
        for (int i = tid; i < 512; i += 256) {
            int plane = (i >= 256);
            int rem = i - plane * 256;
            int m = rem >> 1, q = rem & 1;
            const __half* src = (plane ? W2lB : W2hB) + (size_t)m * 128 + kc + q * 8;
            unsigned d = (unsigned)__cvta_generic_to_shared(
                (plane ? Al : Ah) + m * AW + q * 8);
            CP16(d, src);
        }
        CP_COMMIT();
    };
    auto compute2 = [&](int kc, int s) {
        const __half* Ah = smH + (size_t)s * BUF2;
        const __half* Al = Ah + A_ELEMS;
        wmma::fragment<wmma::matrix_a, 16, 16, 16, __half, wmma::row_major> ah[2], al[2];
        wmma::fragment<wmma::matrix_b, 16, 16, 16, __half, wmma::row_major> bf[4];
#pragma unroll
        for (int i = 0; i < 2; i++) {
            wmma::load_matrix_sync(ah[i], Ah + (wm * 32 + i * 16) * AW, AW);
            wmma::load_matrix_sync(al[i], Al + (wm * 32 + i * 16) * AW, AW);
        }
#pragma unroll
        for (int j = 0; j < 4; j++)
            wmma::load_matrix_sync(bf[j], H + kc * BW + wn * 64 + j * 16, BW);
#pragma unroll
        for (int i = 0; i < 2; i++)
#pragma unroll
            for (int j = 0; j < 4; j++) {
                wmma::mma_sync(acc[i][j], ah[i], bf[j], acc[i][j]);
                wmma::mma_sync(acc[i][j], al[i], bf[j], acc[i][j]);
            }
    };

    {
        const int nch = 128 / KCH;                   // 8
        stage2(0, 0);
        stage2(KCH, 1);
        CP_WAIT(1);
        __syncthreads();
        for (int ic = 0; ic < nch; ic++) {
            compute2(ic * KCH, ic % 3);
            if (ic + 2 < nch) {
                stage2((ic + 2) * KCH, (ic + 2) % 3);
                CP_WAIT(1);
            } else {
                CP_WAIT(0);
            }
            __syncthreads();
        }
    }

    // epilogue 2: acc -> Es -> relu+bias -> global fp16
#pragma unroll
    for (int i = 0; i < 2; i++)
#pragma unroll
        for (int j = 0; j < 4; j++)
            wmma::store_matrix_sync(Es + (wm * 32 + i * 16) * EW + wn * 64 + j * 16,
                                    acc[i][j], EW, wmma::mem_row_major);
    __syncthreads();
    {
        const int m = tid >> 1, seg = tid & 1;
        const float bias2 = kall[(size_t)b * KT + OFF_BMID + m];
        const size_t base = ((size_t)b * 128 + m) * NPIX + n0 + seg * 64;
        const float* er = Es + m * EW + seg * 64;
#pragma unroll
        for (int c = 0; c < 64; c += 2) {
            __half2 o;
            o.x = __float2half_rn(fmaxf(er[c + 0] + bias2, 0.f));
            o.y = __float2half_rn(fmaxf(er[c + 1] + bias2, 0.f));
            *reinterpret_cast<__half2*>(&H2out[base + c]) = o;
        }
    }
}

// ======================================================================
// wmma fp16 GEMM (unchanged from R11): 2-term, 3-stage / 1 sync.
// MBLKS=1 (KCH=32): conv tail; MBLKS=2 (KCH=16): g3 gated update
// ======================================================================
template<int MBLKS>
__global__ void __launch_bounds__(256, 2) gemm_wmma(
    const __half* __restrict__ Wh, const __half* __restrict__ Wl,
    int Ktot,
    const __half* __restrict__ B1, int K1, const __half* __restrict__ B2,
    const float* __restrict__ kall, int boff1, int boff2,
    const float* __restrict__ bias_dir,
    float* __restrict__ outf, __half* __restrict__ outh,
    const float* __restrict__ xold, const float* __restrict__ leakp)
{
    constexpr int MT = MBLKS * 128;
    constexpr int NT = 128 / MBLKS;
    constexpr int KCH = (MBLKS == 1) ? 32 : 16;
    constexpr int KK = KCH / 16;
    constexpr int AP = KCH / 8;
    constexpr int AW = KCH + 8;
    constexpr int BW = (MBLKS == 1) ? 136 : 72;
    constexpr int EW = NT + 4;
    constexpr int BUFE = 2 * MT * AW + KCH * BW;

    extern __shared__ __align__(16) char sm[];
    __half* smB = (__half*)sm;
    float* Es = (float*)sm;

    const int tid = threadIdx.x;
    const int b = blockIdx.y;
    const int n0 = blockIdx.x * NT;
    const int wid = tid >> 5;
    const int wm = (MBLKS == 1) ? (wid >> 1) : wid;
    const int wn = (MBLKS == 1) ? (wid & 1) : 0;

    const __half* WhB = Wh + (size_t)b * MT * Ktot;
    const __half* WlB = Wl + (size_t)b * MT * Ktot;

    wmma::fragment<wmma::accumulator, 16, 16, 16, float> acc[2][4];
#pragma unroll
    for (int i = 0; i < 2; i++)
#pragma unroll
        for (int j = 0; j < 4; j++) wmma::fill_fragment(acc[i][j], 0.f);

    auto stage = [&](int kc, int s) {
        __half* Ahd = smB + (size_t)s * BUFE;
        __half* Ald = Ahd + MT * AW;
        __half* Bfd = Ald + MT * AW;
#pragma unroll
        for (int i = tid; i < MT * AP * 2; i += 256) {
            int plane = (i >= MT * AP);
            int rem = i - plane * MT * AP;
            int m = rem / AP, q = rem - m * AP;
            const __half* src = (plane ? WlB : WhB) + (size_t)m * Ktot + kc + q * 8;
            unsigned d = (unsigned)__cvta_generic_to_shared(
                (plane ? Ald : Ahd) + m * AW + q * 8);
            CP16(d, src);
        }
        const __half* sf; int ch0;
        if (kc < K1) { sf = B1 + (size_t)b * K1 * NPIX; ch0 = kc; }
        else { sf = B2 + (size_t)b * (Ktot - K1) * NPIX; ch0 = kc - K1; }
        constexpr int NC8 = NT / 8;
#pragma unroll
        for (int i = tid; i < KCH * NC8; i += 256) {
            int k = i / NC8, c = (i - k * NC8) * 8;
            const __half* src = sf + (size_t)(ch0 + k) * NPIX + n0 + c;
            unsigned d = (unsigned)__cvta_generic_to_shared(Bfd + k * BW + c);
            CP16(d, src);
        }
        CP_COMMIT();
    };

    auto compute = [&](int s) {
        const __half* Ahd = smB + (size_t)s * BUFE;
        const __half* Ald = Ahd + MT * AW;
        const __half* Bfd = Ald + MT * AW;
#pragma unroll
        for (int kk = 0; kk < KK; kk++) {
            wmma::fragment<wmma::matrix_a, 16, 16, 16, __half, wmma::row_major> ah[2], al[2];
            wmma::fragment<wmma::matrix_b, 16, 16, 16, __half, wmma::row_major> bf[4];
#pragma unroll
            for (int i = 0; i < 2; i++) {
                wmma::load_matrix_sync(ah[i], Ahd + (wm * 32 + i * 16) * AW + kk * 16, AW);
                wmma::load_matrix_sync(al[i], Ald + (wm * 32 + i * 16) * AW + kk * 16, AW);
            }
#pragma unroll
            for (int j = 0; j < 4; j++)
                wmma::load_matrix_sync(bf[j], Bfd + kk * 16 * BW + wn * 64 + j * 16, BW);
#pragma unroll
            for (int i = 0; i < 2; i++)
#pragma unroll
                for (int j = 0; j < 4; j++) {
                    wmma::mma_sync(acc[i][j], ah[i], bf[j], acc[i][j]);
                    wmma::mma_sync(acc[i][j], al[i], bf[j], acc[i][j]);
                }
        }
    };

    const int nch = Ktot / KCH;
    stage(0, 0);
    stage(KCH, 1);
    CP_WAIT(1);
    __syncthreads();
    for (int ic = 0; ic < nch; ic++) {
        compute(ic % 3);
        if (ic + 2 < nch) {
            stage((ic + 2) * KCH, (ic + 2) % 3);
            CP_WAIT(1);
        } else {
            CP_WAIT(0);
        }
        __syncthreads();
    }

#pragma unroll
    for (int i = 0; i < 2; i++)
#pragma unroll
        for (int j = 0; j < 4; j++)
            wmma::store_matrix_sync(Es + (wm * 32 + i * 16) * EW + wn * 64 + j * 16,
                                    acc[i][j], EW, wmma::mem_row_major);
    __syncthreads();

    const int m = tid >> 1, seg = tid & 1;
    if (MBLKS == 1) {
        const float bias = kall ? kall[(size_t)b * KT + boff1 + m] : bias_dir[m];
        const size_t base = ((size_t)b * 128 + m) * NPIX + n0 + seg * 64;
        const float* er = Es + m * EW + seg * 64;
        if (outh) {
#pragma unroll
            for (int c = 0; c < 64; c += 2) {
                __half2 o;
                o.x = __float2half_rn(fmaxf(er[c + 0] + bias, 0.f));
                o.y = __float2half_rn(fmaxf(er[c + 1] + bias, 0.f));
                *reinterpret_cast<__half2*>(&outh[base + c]) = o;
            }
        } else {
#pragma unroll
            for (int c = 0; c < 64; c += 4) {
                float4 o;
                o.x = er[c+0] + bias; o.y = er[c+1] + bias;
                o.z = er[c+2] + bias; o.w = er[c+3] + bias;
                if (xold) {
                    float4 x = *reinterpret_cast<const float4*>(&xold[base + c]);
                    o.x += x.x; o.y += x.y; o.z += x.z; o.w += x.w;
                }
                *reinterpret_cast<float4*>(&outf[base + c]) = o;
            }
        }
    } else {
        const float leak = fminf(fmaxf(leakp[0], 0.001f), 1000.f);
        const float* ka = kall + (size_t)b * KT;
        const float bv = ka[boff1 + m] + ka[boff2 + m];
        const float bg = ka[boff1 + 128 + m] + ka[boff2 + 128 + m];
        const size_t base = ((size_t)b * 128 + m) * NPIX + n0 + seg * 32;
        const float* ev = Es + m * EW + seg * 32;
        const float* eg = Es + (m + 128) * EW + seg * 32;
#pragma unroll
        for (int c = 0; c < 32; c += 4) {
            float4 x = *reinterpret_cast<const float4*>(&xold[base + c]);
            float4 o;
            { float v = ev[c+0] + bv, g = eg[c+0] + bg; o.x = x.x + leak * v / (1.f + __expf(-g)); }
            { float v = ev[c+1] + bv, g = eg[c+1] + bg; o.y = x.y + leak * v / (1.f + __expf(-g)); }
            { float v = ev[c+2] + bv, g = eg[c+2] + bg; o.z = x.z + leak * v / (1.f + __expf(-g)); }
            { float v = ev[c+3] + bv, g = eg[c+3] + bg; o.w = x.w + leak * v / (1.f + __expf(-g)); }
            *reinterpret_cast<float4*>(&outf[base + c]) = o;
        }
    }
}

// ======================================================================
// final 128->3 conv + clip
// ======================================================================
__global__ void __launch_bounds__(256) conv_img_kernel(
    const float* __restrict__ X, const float* __restrict__ W,
    const float* __restrict__ bias,
    float* __restrict__ out_img, float* __restrict__ out_raw)
{
    const int b = blockIdx.y, y0 = blockIdx.x * 4, tid = threadIdx.x;
    const int r = tid >> 6, x = tid & 63;
    __shared__ float sW[3 * 1152];
    __shared__ float sIn[6][66];
    for (int i = tid; i < 3 * 1152; i += 256) sW[i] = W[i];
    float acc[3] = {0.f, 0.f, 0.f};
    const float* Xb = X + (size_t)b * NF * NPIX;
    for (int ci = 0; ci < NF; ci++) {
        __syncthreads();
        for (int i = tid; i < 6 * 66; i += 256) {
            int ry = i / 66, cx = i - ry * 66;
            int gy = y0 - 1 + ry, gx = cx - 1;
            float v = 0.f;
            if ((unsigned)gy < 64u && (unsigned)gx < 64u)
                v = Xb[(size_t)ci * NPIX + gy * 64 + gx];
            sIn[ry][cx] = v;
        }
        __syncthreads();
        float in[9];
#pragma unroll
        for (int dy = 0; dy < 3; dy++)
#pragma unroll
            for (int dx = 0; dx < 3; dx++) in[dy * 3 + dx] = sIn[r + dy][x + dx];
#pragma unroll
        for (int o = 0; o < 3; o++)
#pragma unroll
            for (int j = 0; j < 9; j++)
                acc[o] = fmaf(in[j], sW[o * 1152 + ci * 9 + j], acc[o]);
    }
#pragma unroll
    for (int o = 0; o < 3; o++) {
        float v = acc[o] + bias[o];
        size_t idx = ((size_t)b * 3 + o) * NPIX + (size_t)(y0 + r) * 64 + x;
        out_raw[idx] = v;
        out_img[idx] = fminf(fmaxf(v, -1.f), 1.f);
    }
}

// ======================================================================
extern "C" void kernel_launch(void* const* d_in, const int* in_sizes, int n_in,
                              void* d_out, int out_size)
{
    const float* lat  = (const float*)d_in[0];
    const float* ca   = (const float*)d_in[1];
    const float* leak = (const float*)d_in[2];
    const float* hw   = (const float*)d_in[3];
    const float* hb   = (const float*)d_in[4];
    const float* rw1  = (const float*)d_in[5];
    const float* rb1  = (const float*)d_in[6];
    const float* rw2  = (const float*)d_in[7];
    const float* rb2  = (const float*)d_in[8];
    const float* iw   = (const float*)d_in[9];
    const float* ib   = (const float*)d_in[10];

    float* out = (float*)d_out;
    float* out_img = out;
    float* embs    = out + 98304;
    float* out_raw = out + 98304 + (size_t)17 * 4194304;

    float *kall, *c2;
    __half *pf, *h2f, *colf;
    __half *w1h, *w1l, *w2h, *w2l, *w3h, *w3l, *r1h, *r1l, *r2h, *r2l;
    cudaGetSymbolAddress((void**)&kall, g_kall);
    cudaGetSymbolAddress((void**)&pf,  g_pf);
    cudaGetSymbolAddress((void**)&h2f, g_h2f);
    cudaGetSymbolAddress((void**)&w1h, g_w1h); cudaGetSymbolAddress((void**)&w1l, g_w1l);
    cudaGetSymbolAddress((void**)&w2h, g_w2h); cudaGetSymbolAddress((void**)&w2l, g_w2l);
    cudaGetSymbolAddress((void**)&w3h, g_w3h); cudaGetSymbolAddress((void**)&w3l, g_w3l);
    cudaGetSymbolAddress((void**)&colf, g_colf);
    cudaGetSymbolAddress((void**)&r1h, g_rw1h); cudaGetSymbolAddress((void**)&r1l, g_rw1l);
    cudaGetSymbolAddress((void**)&r2h, g_rw2h); cudaGetSymbolAddress((void**)&r2l, g_rw2l);
    cudaGetSymbolAddress((void**)&c2, g_c2);

    const int SM1 = 87552;   // gemm<1>: 3 x (2*128*40 + 32*136) * 2B
    const int SM2 = 80640;   // gemm<2>: 3 x (2*256*24 + 16*72)  * 2B
    const int SMF = 104448;  // mlp12:   Es(67584) pad to 69632 + H(34816)
    cudaFuncSetAttribute(gemm_wmma<1>, cudaFuncAttributeMaxDynamicSharedMemorySize, SM1);
    cudaFuncSetAttribute(gemm_wmma<2>, cudaFuncAttributeMaxDynamicSharedMemorySize, SM2);
    cudaFuncSetAttribute(mlp12_kernel, cudaFuncAttributeMaxDynamicSharedMemorySize, SMF);

    hyper_kernel<<<KT / 256, 256>>>(lat, hw, hb, kall);
    pack_rw_kernel<<<576, 256>>>(rw1, r1h, r1l);
    pack_rw_kernel<<<576, 256>>>(rw2, r2h, r2l);
    cudaMemcpyAsync(embs, ca, (size_t)4194304 * sizeof(float), cudaMemcpyDeviceToDevice);

    for (int t = 0; t < NCALLS; t++) {
        float* x  = embs + (size_t)t * 4194304;
        float* xn = x + 4194304;

        build_p_kernel<<<dim3(NF, NB), 256>>>(x, pf);
        // h2 = relu(W2 @ relu(W1 @ p + b1) + b2)  [fused, h1 in smem]
        mlp12_kernel<<<dim3(32, NB), 256, SMF>>>(w1h, w1l, w2h, w2l, pf, kall, h2f);
        // dn = W_out@h2 + W_sh@p (+biases); xn = x + leak*val*sigmoid(gate)
        gemm_wmma<2><<<dim3(64, NB), 256, SM2>>>(
            w3h, w3l, 512, h2f, 128, pf,
            kall, OFF_BOUT, OFF_BSH, nullptr, xn, nullptr, x, leak);
    }

    float* xf = embs + (size_t)NCALLS * 4194304;
    // h = relu(conv3x3(xf, rw1) + rb1)  [implicit GEMM, K=1152]
    im2col_f32_kernel<<<147456, 256>>>(xf, colf);
    gemm_wmma<1><<<dim3(32, NB), 256, SM1>>>(
        r1h, r1l, 1152, colf, 1152, nullptr,
        nullptr, 0, 0, rb1, nullptr, pf, nullptr, nullptr);
    // y = xf + conv3x3(h, rw2) + rb2
    im2col_h_kernel<<<147456, 256>>>(pf, colf);
    gemm_wmma<1><<<dim3(32, NB), 256, SM1>>>(
        r2h, r2l, 1152, colf, 1152, nullptr,
        nullptr, 0, 0, rb2, c2, nullptr, xf, nullptr);
    conv_img_kernel<<<dim3(16, NB), 256>>>(c2, iw, ib, out_img, out_raw);
}